// round 1
// baseline (speedup 1.0000x reference)
#include <cuda_runtime.h>
#include <math.h>

#define B_    4
#define C_    192
#define H_    128
#define W_    128
#define HW    16384
#define HEADS 8
#define HD    24
#define C3    576      // 3*C
#define HID   510
#define HID2  1020

// ---------------- scratch (device globals; no allocs) ----------------
__device__ float g_big[(size_t)B_ * HID2 * HW];   // qkv_pre (576ch) then ffn_pre (1020ch)
__device__ float g_qkv[(size_t)B_ * C3 * HW];     // qkv after dwconv, later gated hidden (510ch)
__device__ float g_y  [(size_t)B_ * C_ * HW];     // ln1 out -> attn_out -> ln2 out
__device__ float g_sumsq[B_ * 2 * C_];            // per (b, q/k channel) sum of squares
__device__ float g_attn [B_ * HEADS * HD * HD];   // softmaxed attention matrices

// ---------------- utility: zero the sumsq accumulators ----------------
__global__ void zero_sumsq_kernel() {
    int i = blockIdx.x * blockDim.x + threadIdx.x;
    if (i < B_ * 2 * C_) g_sumsq[i] = 0.0f;
}

// ---------------- channel LayerNorm (per pixel over C=192) ----------------
__global__ void ln_kernel(const float* __restrict__ in,
                          const float* __restrict__ w,
                          const float* __restrict__ bias,
                          float* __restrict__ outp) {
    int idx = blockIdx.x * blockDim.x + threadIdx.x;   // 0 .. B*HW-1
    int b = idx >> 14;
    int p = idx & (HW - 1);
    const float* src = in + (size_t)b * C_ * HW + p;
    float s = 0.f, ss = 0.f;
#pragma unroll 4
    for (int c = 0; c < C_; c++) {
        float v = src[(size_t)c * HW];
        s += v; ss += v * v;
    }
    float mu  = s * (1.0f / C_);
    float var = ss * (1.0f / C_) - mu * mu;
    float rs  = rsqrtf(var + 1e-5f);
    float* dst = outp + (size_t)b * C_ * HW + p;
#pragma unroll 4
    for (int c = 0; c < C_; c++) {
        float v = src[(size_t)c * HW];
        dst[(size_t)c * HW] = (v - mu) * rs * w[c] + bias[c];
    }
}

// ---------------- conv1x1 as GEMM: out[b][m][p] = sum_k W[m][k] * in[b][k][p] ----------
// 128x128 tile, 256 threads, 8x8 per-thread register tile, BK=8.
// mode 0: store; mode 1: store acc + Res; mode 2: Out += acc (in-place accumulate)
__global__ __launch_bounds__(256) void gemm_kernel(
    const float* __restrict__ Wt, const float* __restrict__ In,
    float* __restrict__ Out, const float* __restrict__ Res,
    int M, int K, int mode)
{
    const int b     = blockIdx.z;
    const int nBase = blockIdx.x * 128;
    const int mBase = blockIdx.y * 128;
    const float* in_b = In + (size_t)b * K * HW;

    __shared__ float As[8][132];   // padded to dodge store conflicts
    __shared__ float Bs[8][128];

    const int tid = threadIdx.x;
    const int tx = tid & 15, ty = tid >> 4;

    float acc[8][8];
#pragma unroll
    for (int i = 0; i < 8; i++)
#pragma unroll
        for (int j = 0; j < 8; j++) acc[i][j] = 0.f;

    const int aRow = tid >> 1;          // 0..127 (m)
    const int aCol = (tid & 1) * 4;     // 0 or 4 (k)
    const int bRow = tid >> 5;          // 0..7   (k)
    const int bCol = (tid & 31) * 4;    // 0..124 (n)

    for (int k0 = 0; k0 < K; k0 += 8) {
        // A tile (W is row-major [M,K]; stored transposed into As[k][m]; scalar loads, alignment-safe)
        {
            float a0 = 0.f, a1 = 0.f, a2 = 0.f, a3 = 0.f;
            int m = mBase + aRow;
            if (m < M) {
                const float* wr = Wt + (size_t)m * K + k0 + aCol;
                int rem = K - (k0 + aCol);
                if (rem >= 4)      { a0 = wr[0]; a1 = wr[1]; a2 = wr[2]; a3 = wr[3]; }
                else {
                    if (rem > 0) a0 = wr[0];
                    if (rem > 1) a1 = wr[1];
                    if (rem > 2) a2 = wr[2];
                }
            }
            As[aCol + 0][aRow] = a0;
            As[aCol + 1][aRow] = a1;
            As[aCol + 2][aRow] = a2;
            As[aCol + 3][aRow] = a3;
        }
        // B tile (activations, contiguous in p -> float4)
        {
            float4 bv = make_float4(0.f, 0.f, 0.f, 0.f);
            int kk = k0 + bRow;
            if (kk < K) bv = *(const float4*)(in_b + (size_t)kk * HW + nBase + bCol);
            *(float4*)&Bs[bRow][bCol] = bv;
        }
        __syncthreads();

#pragma unroll
        for (int kk = 0; kk < 8; kk++) {
            float a[8], bb[8];
            *(float4*)(a)      = *(const float4*)&As[kk][ty * 8];
            *(float4*)(a + 4)  = *(const float4*)&As[kk][ty * 8 + 4];
            *(float4*)(bb)     = *(const float4*)&Bs[kk][tx * 8];
            *(float4*)(bb + 4) = *(const float4*)&Bs[kk][tx * 8 + 4];
#pragma unroll
            for (int i = 0; i < 8; i++)
#pragma unroll
                for (int j = 0; j < 8; j++)
                    acc[i][j] += a[i] * bb[j];
        }
        __syncthreads();
    }

    // epilogue
#pragma unroll
    for (int i = 0; i < 8; i++) {
        int m = mBase + ty * 8 + i;
        if (m >= M) break;
        size_t off = ((size_t)b * M + m) * HW + nBase + tx * 8;
        float4 v0 = make_float4(acc[i][0], acc[i][1], acc[i][2], acc[i][3]);
        float4 v1 = make_float4(acc[i][4], acc[i][5], acc[i][6], acc[i][7]);
        if (mode == 1) {
            float4 r0 = *(const float4*)(Res + off);
            float4 r1 = *(const float4*)(Res + off + 4);
            v0.x += r0.x; v0.y += r0.y; v0.z += r0.z; v0.w += r0.w;
            v1.x += r1.x; v1.y += r1.y; v1.z += r1.z; v1.w += r1.w;
        } else if (mode == 2) {
            float4 r0 = *(const float4*)(Out + off);
            float4 r1 = *(const float4*)(Out + off + 4);
            v0.x += r0.x; v0.y += r0.y; v0.z += r0.z; v0.w += r0.w;
            v1.x += r1.x; v1.y += r1.y; v1.z += r1.z; v1.w += r1.w;
        }
        *(float4*)(Out + off)     = v0;
        *(float4*)(Out + off + 4) = v1;
    }
}

// ---------------- depthwise 3x3 on qkv (576 ch) + q/k sum-of-squares ----------------
__global__ void dwqkv_kernel(const float* __restrict__ wdw) {
    int y = blockIdx.x, c = blockIdx.y, b = blockIdx.z, tid = threadIdx.x;
    __shared__ float s[3][130];
    __shared__ float wsum[4];
    const float* src = g_big + ((size_t)(b * C3 + c)) * HW;
#pragma unroll
    for (int r = 0; r < 3; r++) {
        int yy = y + r - 1;
        s[r][tid + 1] = (yy >= 0 && yy < H_) ? src[yy * W_ + tid] : 0.f;
    }
    if (tid < 3) { s[tid][0] = 0.f; s[tid][129] = 0.f; }
    __syncthreads();
    const float* wp = wdw + c * 9;
    float v = wp[0]*s[0][tid] + wp[1]*s[0][tid+1] + wp[2]*s[0][tid+2]
            + wp[3]*s[1][tid] + wp[4]*s[1][tid+1] + wp[5]*s[1][tid+2]
            + wp[6]*s[2][tid] + wp[7]*s[2][tid+1] + wp[8]*s[2][tid+2];
    g_qkv[((size_t)(b * C3 + c)) * HW + y * W_ + tid] = v;

    if (c < 2 * C_) {  // q or k channel -> accumulate sum of squares over HW
        float sq = v * v;
#pragma unroll
        for (int off = 16; off; off >>= 1) sq += __shfl_xor_sync(0xffffffffu, sq, off);
        if ((tid & 31) == 0) wsum[tid >> 5] = sq;
        __syncthreads();
        if (tid == 0)
            atomicAdd(&g_sumsq[b * 2 * C_ + c], wsum[0] + wsum[1] + wsum[2] + wsum[3]);
    }
}

// ---------------- attention scores + softmax: per (b, h, 4 d-rows) ----------------
__global__ __launch_bounds__(256) void attn_kernel(const float* __restrict__ temp) {
    int dg = blockIdx.x, h = blockIdx.y, b = blockIdx.z, tid = threadIdx.x;
    const float* base  = g_qkv + (size_t)b * C3 * HW;
    const float* q0    = base + (size_t)(h * HD + dg * 4) * HW;
    const float* kbase = base + (size_t)(C_ + h * HD) * HW;

    float acc[4][24];
#pragma unroll
    for (int i = 0; i < 4; i++)
#pragma unroll
        for (int c = 0; c < 24; c++) acc[i][c] = 0.f;

    for (int p = tid; p < HW; p += 256) {
        float kv[24];
#pragma unroll
        for (int c = 0; c < 24; c++) kv[c] = kbase[(size_t)c * HW + p];
#pragma unroll
        for (int i = 0; i < 4; i++) {
            float qv = q0[(size_t)i * HW + p];
#pragma unroll
            for (int c = 0; c < 24; c++) acc[i][c] += qv * kv[c];
        }
    }
    // warp butterfly then cross-warp reduce
#pragma unroll
    for (int i = 0; i < 4; i++)
#pragma unroll
        for (int c = 0; c < 24; c++)
#pragma unroll
            for (int off = 16; off; off >>= 1)
                acc[i][c] += __shfl_xor_sync(0xffffffffu, acc[i][c], off);

    __shared__ float red[8][96];
    __shared__ float S[96];
    int w = tid >> 5, lane = tid & 31;
    if (lane == 0) {
#pragma unroll
        for (int i = 0; i < 4; i++)
#pragma unroll
            for (int c = 0; c < 24; c++) red[w][i * 24 + c] = acc[i][c];
    }
    __syncthreads();
    if (tid < 96) {
        float s = 0.f;
#pragma unroll
        for (int ww = 0; ww < 8; ww++) s += red[ww][tid];
        S[tid] = s;
    }
    __syncthreads();

    if (tid < 4) {
        int d = dg * 4 + tid;
        float sq = g_sumsq[b * 2 * C_ + h * HD + d];
        float rq = 1.0f / fmaxf(sqrtf(sq), 1e-12f);
        float t  = temp[h];
        float row[24];
        float mx = -3.4e38f;
#pragma unroll
        for (int c = 0; c < 24; c++) {
            float sk = g_sumsq[b * 2 * C_ + C_ + h * HD + c];
            float rk = 1.0f / fmaxf(sqrtf(sk), 1e-12f);
            row[c] = S[tid * 24 + c] * rq * rk * t;
            mx = fmaxf(mx, row[c]);
        }
        float sum = 0.f;
#pragma unroll
        for (int c = 0; c < 24; c++) { row[c] = expf(row[c] - mx); sum += row[c]; }
        float inv = 1.0f / sum;
        float* ap = g_attn + (((size_t)(b * HEADS + h)) * HD + d) * HD;
#pragma unroll
        for (int c = 0; c < 24; c++) ap[c] = row[c] * inv;
    }
}

// ---------------- out = attn @ v, writes into g_y (channel layout) ----------------
__global__ void av_kernel() {
    int tid = threadIdx.x;
    int p = blockIdx.x * 256 + tid;
    int h = blockIdx.y, b = blockIdx.z;
    __shared__ float A[HD * HD];
    const float* ap = g_attn + ((size_t)(b * HEADS + h)) * HD * HD;
    for (int i = tid; i < HD * HD; i += 256) A[i] = ap[i];
    __syncthreads();
    const float* vb = g_qkv + (size_t)b * C3 * HW + (size_t)(2 * C_ + h * HD) * HW;
    float v[24];
#pragma unroll
    for (int c = 0; c < 24; c++) v[c] = vb[(size_t)c * HW + p];
    float* ob = g_y + (size_t)b * C_ * HW + (size_t)(h * HD) * HW;
#pragma unroll
    for (int d = 0; d < 24; d++) {
        float s = 0.f;
#pragma unroll
        for (int c = 0; c < 24; c++) s += A[d * 24 + c] * v[c];
        ob[(size_t)d * HW + p] = s;
    }
}

// ---------------- FFN depthwise 3x3 + GELU gate (fused) ----------------
__global__ void dwgate_kernel(const float* __restrict__ wdw) {
    int y = blockIdx.x, j = blockIdx.y, b = blockIdx.z, tid = threadIdx.x;
    __shared__ float s1[3][130];
    __shared__ float s2[3][130];
    const float* src1 = g_big + ((size_t)(b * HID2 + j)) * HW;
    const float* src2 = g_big + ((size_t)(b * HID2 + j + HID)) * HW;
#pragma unroll
    for (int r = 0; r < 3; r++) {
        int yy = y + r - 1;
        bool ok = (yy >= 0 && yy < H_);
        s1[r][tid + 1] = ok ? src1[yy * W_ + tid] : 0.f;
        s2[r][tid + 1] = ok ? src2[yy * W_ + tid] : 0.f;
    }
    if (tid < 3) { s1[tid][0] = 0.f; s1[tid][129] = 0.f; s2[tid][0] = 0.f; s2[tid][129] = 0.f; }
    __syncthreads();
    const float* w1 = wdw + j * 9;
    const float* w2 = wdw + (j + HID) * 9;
    float v1 = w1[0]*s1[0][tid] + w1[1]*s1[0][tid+1] + w1[2]*s1[0][tid+2]
             + w1[3]*s1[1][tid] + w1[4]*s1[1][tid+1] + w1[5]*s1[1][tid+2]
             + w1[6]*s1[2][tid] + w1[7]*s1[2][tid+1] + w1[8]*s1[2][tid+2];
    float v2 = w2[0]*s2[0][tid] + w2[1]*s2[0][tid+1] + w2[2]*s2[0][tid+2]
             + w2[3]*s2[1][tid] + w2[4]*s2[1][tid+1] + w2[5]*s2[1][tid+2]
             + w2[6]*s2[2][tid] + w2[7]*s2[2][tid+1] + w2[8]*s2[2][tid+2];
    float g = 0.5f * v1 * (1.0f + erff(v1 * 0.70710678118654752440f));  // exact GELU
    g_qkv[((size_t)(b * HID + j)) * HW + y * W_ + tid] = g * v2;
}

// ---------------- launch ----------------
extern "C" void kernel_launch(void* const* d_in, const int* in_sizes, int n_in,
                              void* d_out, int out_size) {
    const float* x      = (const float*)d_in[0];
    const float* temp   = (const float*)d_in[1];
    const float* ln1w   = (const float*)d_in[2];
    const float* ln1b   = (const float*)d_in[3];
    const float* ln2w   = (const float*)d_in[4];
    const float* ln2b   = (const float*)d_in[5];
    const float* wqkv   = (const float*)d_in[6];
    const float* wqkvdw = (const float*)d_in[7];
    const float* wproj  = (const float*)d_in[8];
    const float* win    = (const float*)d_in[9];
    const float* wdw    = (const float*)d_in[10];
    const float* wout   = (const float*)d_in[11];
    float* out = (float*)d_out;

    float *pBig, *pQkv, *pY;
    cudaGetSymbolAddress((void**)&pBig, g_big);
    cudaGetSymbolAddress((void**)&pQkv, g_qkv);
    cudaGetSymbolAddress((void**)&pY,   g_y);

    // --- attention branch ---
    zero_sumsq_kernel<<<6, 256>>>();
    ln_kernel<<<(B_ * HW) / 256, 256>>>(x, ln1w, ln1b, pY);
    gemm_kernel<<<dim3(128, 5, B_), 256>>>(wqkv, pY, pBig, nullptr, C3, C_, 0);   // qkv 1x1
    dwqkv_kernel<<<dim3(H_, C3, B_), 128>>>(wqkvdw);                               // dw3x3 + sumsq
    attn_kernel<<<dim3(HD / 4, HEADS, B_), 256>>>(temp);                           // scores+softmax
    av_kernel<<<dim3(HW / 256, HEADS, B_), 256>>>();                               // A @ V -> g_y
    gemm_kernel<<<dim3(128, 2, B_), 256>>>(wproj, pY, out, x, C_, C_, 1);          // proj + residual -> d_out (=x1)

    // --- FFN branch ---
    ln_kernel<<<(B_ * HW) / 256, 256>>>(out, ln2w, ln2b, pY);
    gemm_kernel<<<dim3(128, 8, B_), 256>>>(win, pY, pBig, nullptr, HID2, C_, 0);   // 192 -> 1020
    dwgate_kernel<<<dim3(H_, HID, B_), 128>>>(wdw);                                // dw3x3 + gelu gate -> 510ch
    gemm_kernel<<<dim3(128, 2, B_), 256>>>(wout, pQkv, out, nullptr, C_, HID, 2);  // 510 -> 192, += into d_out
}

// round 2
// speedup vs baseline: 1.6332x; 1.6332x over previous
#include <cuda_runtime.h>
#include <math.h>

#define B_    4
#define C_    192
#define H_    128
#define W_    128
#define HW    16384
#define HEADS 8
#define HD    24
#define C3    576
#define HID   510
#define HID2  1020

// ---------------- scratch (device globals; no allocs) ----------------
__device__ float g_big[(size_t)B_ * HID2 * HW];   // qkv_pre (576ch) then ffn_pre (1020ch)
__device__ float g_qkv[(size_t)B_ * C3 * HW];     // qkv after dwconv, later gated hidden (510ch)
__device__ float g_y  [(size_t)B_ * C_ * HW];     // ln1 out -> attn_out -> ln2 out
__device__ float g_sumsq[B_ * 2 * C_];
__device__ float g_attn [B_ * HEADS * HD * HD];

__global__ void zero_sumsq_kernel() {
    int i = blockIdx.x * blockDim.x + threadIdx.x;
    if (i < B_ * 2 * C_) g_sumsq[i] = 0.0f;
}

// ---------------- channel LayerNorm (per pixel over C=192) ----------------
__global__ void ln_kernel(const float* __restrict__ in,
                          const float* __restrict__ w,
                          const float* __restrict__ bias,
                          float* __restrict__ outp) {
    int idx = blockIdx.x * blockDim.x + threadIdx.x;
    int b = idx >> 14;
    int p = idx & (HW - 1);
    const float* src = in + (size_t)b * C_ * HW + p;
    float s = 0.f, ss = 0.f;
#pragma unroll 4
    for (int c = 0; c < C_; c++) {
        float v = src[(size_t)c * HW];
        s += v; ss += v * v;
    }
    float mu  = s * (1.0f / C_);
    float var = ss * (1.0f / C_) - mu * mu;
    float rs  = rsqrtf(var + 1e-5f);
    float* dst = outp + (size_t)b * C_ * HW + p;
#pragma unroll 4
    for (int c = 0; c < C_; c++) {
        float v = src[(size_t)c * HW];
        dst[(size_t)c * HW] = (v - mu) * rs * w[c] + bias[c];
    }
}

// ---------------- tf32 tensor-core GEMM ----------------
// out[b][m][p] = sum_k W[m][k] * In[b][k][p]
// 128x128 tile, BK=16, 8 warps (2 m x 4 n), warp tile 64x32, mma m16n8k8 tf32.
// mode 0: store; 1: store + Res; 2: Out += acc
__device__ __forceinline__ unsigned f2tf32(float f) {
    unsigned u;
    asm("cvt.rna.tf32.f32 %0, %1;" : "=r"(u) : "f"(f));
    return u;
}

#define GBM 128
#define GBN 128
#define GBK 16
#define SSTR 136   // GBN + 8 -> conflict-free fragment loads

__global__ __launch_bounds__(256) void gemm_tc(
    const float* __restrict__ Wt, const float* __restrict__ In,
    float* __restrict__ Out, const float* __restrict__ Res,
    int M, int K, int mode)
{
    __shared__ unsigned As[GBK][SSTR];   // As[k][m] (tf32 bits)
    __shared__ unsigned Bs[GBK][SSTR];   // Bs[k][n]

    const int b     = blockIdx.z;
    const int nBase = blockIdx.x * GBN;
    const int mBase = blockIdx.y * GBM;
    const float* in_b = In + (size_t)b * K * HW;

    const int tid  = threadIdx.x;
    const int wid  = tid >> 5, lane = tid & 31;
    const int warpM = wid >> 2;          // 0..1  -> 64 rows
    const int warpN = wid & 3;           // 0..3  -> 32 cols
    const int g = lane >> 2, tig = lane & 3;

    float acc[4][4][4];
#pragma unroll
    for (int i = 0; i < 4; i++)
#pragma unroll
        for (int j = 0; j < 4; j++)
#pragma unroll
            for (int r = 0; r < 4; r++) acc[i][j][r] = 0.f;

    // A-load mapping: thread t -> m = t>>1, k-chunk = (t&1)*8
    const int amRow = tid >> 1;
    const int akOff = (tid & 1) * 8;
    // B-load mapping: thread t -> k = t>>4, n = (t&15)*8
    const int bkRow = tid >> 4;
    const int bnOff = (tid & 15) * 8;

    for (int k0 = 0; k0 < K; k0 += GBK) {
        // ---- load A tile (weights, row-major [M,K]) as tf32 into As[k][m]
        {
            const int m = mBase + amRow;
            const bool mok = (m < M);
            const float* wr = Wt + (size_t)(mok ? m : 0) * K;
#pragma unroll
            for (int i = 0; i < 8; i++) {
                int kg = k0 + akOff + i;
                float v = (mok && kg < K) ? wr[kg] : 0.f;
                As[akOff + i][amRow] = f2tf32(v);
            }
        }
        // ---- load B tile (activations, contiguous in p)
        {
            int kk = k0 + bkRow;
            float4 v0 = make_float4(0.f, 0.f, 0.f, 0.f);
            float4 v1 = make_float4(0.f, 0.f, 0.f, 0.f);
            if (kk < K) {
                const float* p = in_b + (size_t)kk * HW + nBase + bnOff;
                v0 = *(const float4*)p;
                v1 = *(const float4*)(p + 4);
            }
            Bs[bkRow][bnOff + 0] = f2tf32(v0.x);
            Bs[bkRow][bnOff + 1] = f2tf32(v0.y);
            Bs[bkRow][bnOff + 2] = f2tf32(v0.z);
            Bs[bkRow][bnOff + 3] = f2tf32(v0.w);
            Bs[bkRow][bnOff + 4] = f2tf32(v1.x);
            Bs[bkRow][bnOff + 5] = f2tf32(v1.y);
            Bs[bkRow][bnOff + 6] = f2tf32(v1.z);
            Bs[bkRow][bnOff + 7] = f2tf32(v1.w);
        }
        __syncthreads();

#pragma unroll
        for (int ks = 0; ks < 2; ks++) {
            const int kb = ks * 8;
            unsigned af[4][4], bf[4][2];
#pragma unroll
            for (int mt = 0; mt < 4; mt++) {
                int mr = warpM * 64 + mt * 16;
                af[mt][0] = As[kb + tig    ][mr + g    ];
                af[mt][1] = As[kb + tig    ][mr + g + 8];
                af[mt][2] = As[kb + tig + 4][mr + g    ];
                af[mt][3] = As[kb + tig + 4][mr + g + 8];
            }
#pragma unroll
            for (int nt = 0; nt < 4; nt++) {
                int nr = warpN * 32 + nt * 8;
                bf[nt][0] = Bs[kb + tig    ][nr + g];
                bf[nt][1] = Bs[kb + tig + 4][nr + g];
            }
#pragma unroll
            for (int mt = 0; mt < 4; mt++)
#pragma unroll
                for (int nt = 0; nt < 4; nt++) {
                    asm volatile(
                        "mma.sync.aligned.m16n8k8.row.col.f32.tf32.tf32.f32 "
                        "{%0,%1,%2,%3}, {%4,%5,%6,%7}, {%8,%9}, {%0,%1,%2,%3};"
                        : "+f"(acc[mt][nt][0]), "+f"(acc[mt][nt][1]),
                          "+f"(acc[mt][nt][2]), "+f"(acc[mt][nt][3])
                        : "r"(af[mt][0]), "r"(af[mt][1]), "r"(af[mt][2]), "r"(af[mt][3]),
                          "r"(bf[nt][0]), "r"(bf[nt][1]));
                }
        }
        __syncthreads();
    }

    // ---- epilogue ----
#pragma unroll
    for (int mt = 0; mt < 4; mt++) {
#pragma unroll
        for (int half = 0; half < 2; half++) {
            int m = mBase + warpM * 64 + mt * 16 + g + half * 8;
            if (m >= M) continue;
#pragma unroll
            for (int nt = 0; nt < 4; nt++) {
                int n = nBase + warpN * 32 + nt * 8 + 2 * tig;
                size_t off = ((size_t)b * M + m) * HW + n;
                float2 v;
                v.x = acc[mt][nt][half * 2 + 0];
                v.y = acc[mt][nt][half * 2 + 1];
                if (mode == 1) {
                    float2 r = *(const float2*)(Res + off);
                    v.x += r.x; v.y += r.y;
                } else if (mode == 2) {
                    float2 r = *(const float2*)(Out + off);
                    v.x += r.x; v.y += r.y;
                }
                *(float2*)(Out + off) = v;
            }
        }
    }
}

// ---------------- depthwise 3x3 on qkv (576 ch), 16-row tiles, + q/k sumsq ----------------
__global__ __launch_bounds__(256) void dwqkv_kernel(const float* __restrict__ wdw) {
    const int y0 = blockIdx.x * 16;
    const int c  = blockIdx.y;
    const int b  = blockIdx.z;
    const int tid = threadIdx.x;
    __shared__ float s[18][132];
    const float* src = g_big + ((size_t)(b * C3 + c)) * HW;
    for (int i = tid; i < 18 * 130; i += 256) {
        int r = i / 130, col = i - r * 130;
        int y = y0 + r - 1, x = col - 1;
        s[r][col] = (y >= 0 && y < H_ && x >= 0 && x < W_) ? src[y * W_ + x] : 0.f;
    }
    __syncthreads();
    const float* wp = wdw + c * 9;
    const float w0 = wp[0], w1 = wp[1], w2 = wp[2], w3 = wp[3], w4 = wp[4],
                w5 = wp[5], w6 = wp[6], w7 = wp[7], w8 = wp[8];
    float sq = 0.f;
    float* dst = g_qkv + ((size_t)(b * C3 + c)) * HW;
#pragma unroll
    for (int kk = 0; kk < 8; kk++) {
        int j = tid + kk * 256;
        int r = j >> 7, col = j & 127;
        float v = w0 * s[r    ][col] + w1 * s[r    ][col + 1] + w2 * s[r    ][col + 2]
                + w3 * s[r + 1][col] + w4 * s[r + 1][col + 1] + w5 * s[r + 1][col + 2]
                + w6 * s[r + 2][col] + w7 * s[r + 2][col + 1] + w8 * s[r + 2][col + 2];
        dst[(y0 + r) * W_ + col] = v;
        sq += v * v;
    }
    if (c < 2 * C_) {
#pragma unroll
        for (int o = 16; o; o >>= 1) sq += __shfl_xor_sync(0xffffffffu, sq, o);
        __shared__ float ws[8];
        if ((tid & 31) == 0) ws[tid >> 5] = sq;
        __syncthreads();
        if (tid == 0) {
            float t = 0.f;
#pragma unroll
            for (int i = 0; i < 8; i++) t += ws[i];
            atomicAdd(&g_sumsq[b * 2 * C_ + c], t);
        }
    }
}

// ---------------- attention scores + softmax: per (b, h, 4 d-rows) ----------------
__global__ __launch_bounds__(256) void attn_kernel(const float* __restrict__ temp) {
    int dg = blockIdx.x, h = blockIdx.y, b = blockIdx.z, tid = threadIdx.x;
    const float* base  = g_qkv + (size_t)b * C3 * HW;
    const float* q0    = base + (size_t)(h * HD + dg * 4) * HW;
    const float* kbase = base + (size_t)(C_ + h * HD) * HW;

    float acc[4][24];
#pragma unroll
    for (int i = 0; i < 4; i++)
#pragma unroll
        for (int c = 0; c < 24; c++) acc[i][c] = 0.f;

    for (int p = tid; p < HW; p += 256) {
        float kv[24];
#pragma unroll
        for (int c = 0; c < 24; c++) kv[c] = kbase[(size_t)c * HW + p];
#pragma unroll
        for (int i = 0; i < 4; i++) {
            float qv = q0[(size_t)i * HW + p];
#pragma unroll
            for (int c = 0; c < 24; c++) acc[i][c] += qv * kv[c];
        }
    }
#pragma unroll
    for (int i = 0; i < 4; i++)
#pragma unroll
        for (int c = 0; c < 24; c++)
#pragma unroll
            for (int o = 16; o; o >>= 1)
                acc[i][c] += __shfl_xor_sync(0xffffffffu, acc[i][c], o);

    __shared__ float red[8][96];
    __shared__ float S[96];
    int w = tid >> 5, lane = tid & 31;
    if (lane == 0) {
#pragma unroll
        for (int i = 0; i < 4; i++)
#pragma unroll
            for (int c = 0; c < 24; c++) red[w][i * 24 + c] = acc[i][c];
    }
    __syncthreads();
    if (tid < 96) {
        float s = 0.f;
#pragma unroll
        for (int ww = 0; ww < 8; ww++) s += red[ww][tid];
        S[tid] = s;
    }
    __syncthreads();

    if (tid < 4) {
        int d = dg * 4 + tid;
        float sq = g_sumsq[b * 2 * C_ + h * HD + d];
        float rq = 1.0f / fmaxf(sqrtf(sq), 1e-12f);
        float t  = temp[h];
        float row[24];
        float mx = -3.4e38f;
#pragma unroll
        for (int c = 0; c < 24; c++) {
            float sk = g_sumsq[b * 2 * C_ + C_ + h * HD + c];
            float rk = 1.0f / fmaxf(sqrtf(sk), 1e-12f);
            row[c] = S[tid * 24 + c] * rq * rk * t;
            mx = fmaxf(mx, row[c]);
        }
        float sum = 0.f;
#pragma unroll
        for (int c = 0; c < 24; c++) { row[c] = expf(row[c] - mx); sum += row[c]; }
        float inv = 1.0f / sum;
        float* ap = g_attn + (((size_t)(b * HEADS + h)) * HD + d) * HD;
#pragma unroll
        for (int c = 0; c < 24; c++) ap[c] = row[c] * inv;
    }
}

// ---------------- out = attn @ v -> g_y ----------------
__global__ void av_kernel() {
    int tid = threadIdx.x;
    int p = blockIdx.x * 256 + tid;
    int h = blockIdx.y, b = blockIdx.z;
    __shared__ float A[HD * HD];
    const float* ap = g_attn + ((size_t)(b * HEADS + h)) * HD * HD;
    for (int i = tid; i < HD * HD; i += 256) A[i] = ap[i];
    __syncthreads();
    const float* vb = g_qkv + (size_t)b * C3 * HW + (size_t)(2 * C_ + h * HD) * HW;
    float v[24];
#pragma unroll
    for (int c = 0; c < 24; c++) v[c] = vb[(size_t)c * HW + p];
    float* ob = g_y + (size_t)b * C_ * HW + (size_t)(h * HD) * HW;
#pragma unroll
    for (int d = 0; d < 24; d++) {
        float s = 0.f;
#pragma unroll
        for (int c = 0; c < 24; c++) s += A[d * 24 + c] * v[c];
        ob[(size_t)d * HW + p] = s;
    }
}

// ---------------- FFN depthwise 3x3 + GELU gate, 16-row tiles ----------------
__global__ __launch_bounds__(256) void dwgate_kernel(const float* __restrict__ wdw) {
    const int y0 = blockIdx.x * 16;
    const int j  = blockIdx.y;
    const int b  = blockIdx.z;
    const int tid = threadIdx.x;
    __shared__ float s1[18][132];
    __shared__ float s2[18][132];
    const float* src1 = g_big + ((size_t)(b * HID2 + j)) * HW;
    const float* src2 = g_big + ((size_t)(b * HID2 + j + HID)) * HW;
    for (int i = tid; i < 18 * 130; i += 256) {
        int r = i / 130, col = i - r * 130;
        int y = y0 + r - 1, x = col - 1;
        bool ok = (y >= 0 && y < H_ && x >= 0 && x < W_);
        s1[r][col] = ok ? src1[y * W_ + x] : 0.f;
        s2[r][col] = ok ? src2[y * W_ + x] : 0.f;
    }
    __syncthreads();
    const float* wa = wdw + j * 9;
    const float* wb = wdw + (j + HID) * 9;
    float a0 = wa[0], a1 = wa[1], a2 = wa[2], a3 = wa[3], a4 = wa[4],
          a5 = wa[5], a6 = wa[6], a7 = wa[7], a8 = wa[8];
    float b0 = wb[0], b1 = wb[1], b2 = wb[2], b3 = wb[3], b4 = wb[4],
          b5 = wb[5], b6 = wb[6], b7 = wb[7], b8 = wb[8];
    float* dst = g_qkv + ((size_t)(b * HID + j)) * HW;
#pragma unroll
    for (int kk = 0; kk < 8; kk++) {
        int jj = tid + kk * 256;
        int r = jj >> 7, col = jj & 127;
        float v1 = a0 * s1[r    ][col] + a1 * s1[r    ][col + 1] + a2 * s1[r    ][col + 2]
                 + a3 * s1[r + 1][col] + a4 * s1[r + 1][col + 1] + a5 * s1[r + 1][col + 2]
                 + a6 * s1[r + 2][col] + a7 * s1[r + 2][col + 1] + a8 * s1[r + 2][col + 2];
        float v2 = b0 * s2[r    ][col] + b1 * s2[r    ][col + 1] + b2 * s2[r    ][col + 2]
                 + b3 * s2[r + 1][col] + b4 * s2[r + 1][col + 1] + b5 * s2[r + 1][col + 2]
                 + b6 * s2[r + 2][col] + b7 * s2[r + 2][col + 1] + b8 * s2[r + 2][col + 2];
        float gl = 0.5f * v1 * (1.0f + erff(v1 * 0.70710678118654752440f));
        dst[(y0 + r) * W_ + col] = gl * v2;
    }
}

// ---------------- launch ----------------
extern "C" void kernel_launch(void* const* d_in, const int* in_sizes, int n_in,
                              void* d_out, int out_size) {
    const float* x      = (const float*)d_in[0];
    const float* temp   = (const float*)d_in[1];
    const float* ln1w   = (const float*)d_in[2];
    const float* ln1b   = (const float*)d_in[3];
    const float* ln2w   = (const float*)d_in[4];
    const float* ln2b   = (const float*)d_in[5];
    const float* wqkv   = (const float*)d_in[6];
    const float* wqkvdw = (const float*)d_in[7];
    const float* wproj  = (const float*)d_in[8];
    const float* win    = (const float*)d_in[9];
    const float* wdw    = (const float*)d_in[10];
    const float* wout   = (const float*)d_in[11];
    float* out = (float*)d_out;

    float *pBig, *pQkv, *pY;
    cudaGetSymbolAddress((void**)&pBig, g_big);
    cudaGetSymbolAddress((void**)&pQkv, g_qkv);
    cudaGetSymbolAddress((void**)&pY,   g_y);

    // --- attention branch ---
    zero_sumsq_kernel<<<6, 256>>>();
    ln_kernel<<<(B_ * HW) / 256, 256>>>(x, ln1w, ln1b, pY);
    gemm_tc<<<dim3(128, 5, B_), 256>>>(wqkv, pY, pBig, nullptr, C3, C_, 0);      // qkv 1x1
    dwqkv_kernel<<<dim3(8, C3, B_), 256>>>(wqkvdw);                               // dw3x3 + sumsq
    attn_kernel<<<dim3(HD / 4, HEADS, B_), 256>>>(temp);                          // scores+softmax
    av_kernel<<<dim3(HW / 256, HEADS, B_), 256>>>();                              // A @ V -> g_y
    gemm_tc<<<dim3(128, 2, B_), 256>>>(wproj, pY, out, x, C_, C_, 1);             // proj + residual

    // --- FFN branch ---
    ln_kernel<<<(B_ * HW) / 256, 256>>>(out, ln2w, ln2b, pY);
    gemm_tc<<<dim3(128, 8, B_), 256>>>(win, pY, pBig, nullptr, HID2, C_, 0);      // 192 -> 1020
    dwgate_kernel<<<dim3(8, HID, B_), 256>>>(wdw);                                // dw3x3 + gelu gate
    gemm_tc<<<dim3(128, 2, B_), 256>>>(wout, pQkv, out, nullptr, C_, HID, 2);     // 510 -> 192, +=
}

// round 5
// speedup vs baseline: 3.1896x; 1.9530x over previous
#include <cuda_runtime.h>
#include <cuda_bf16.h>
#include <stdint.h>
#include <math.h>

#define B_    4
#define C_    192
#define H_    128
#define W_    128
#define HW    16384
#define HEADS 8
#define HD    24
#define C3    576
#define HID   510
#define HID2  1020
#define KPAD  512      // padded K for ffn_out gemm

// ---------------- scratch (device globals; no allocs) ----------------
__device__ __nv_bfloat16 gb_big[(size_t)B_ * HID2 * HW]; // qkv_pre(576ch) / ffn_pre(1020ch), b-stride HID2
__device__ __nv_bfloat16 gb_qkv[(size_t)B_ * C3 * HW];   // dw out (576ch) / gated hidden (512ch), b-stride C3
__device__ __nv_bfloat16 gb_y  [(size_t)B_ * C_ * HW];   // ln out / attn out, b-stride C_
__device__ float g_sumsq[B_ * 2 * C_];
__device__ float g_attn [B_ * HEADS * HD * HD];
// bf16 weights (row-padded to multiples of 128; wout also K-padded to 512)
__device__ __nv_bfloat16 gw_qkv[640 * 192];
__device__ __nv_bfloat16 gw_proj[256 * 192];
__device__ __nv_bfloat16 gw_in [1024 * 192];
__device__ __nv_bfloat16 gw_out[256 * KPAD];

// ---------------- prep: convert/pad weights to bf16, zero sumsq ----------------
__global__ void prep_kernel(const float* __restrict__ wqkv, const float* __restrict__ wproj,
                            const float* __restrict__ win,  const float* __restrict__ wout) {
    const int N1 = 640 * 192, N2 = 256 * 192, N3 = 1024 * 192, N4 = 256 * KPAD;
    const int TOT = N1 + N2 + N3 + N4 + B_ * 2 * C_;
    for (int i = blockIdx.x * blockDim.x + threadIdx.x; i < TOT; i += gridDim.x * blockDim.x) {
        int j = i;
        if (j < N1) {
            int m = j / 192, k = j - m * 192;
            gw_qkv[j] = __float2bfloat16(m < C3 ? wqkv[m * 192 + k] : 0.f);
            continue;
        }
        j -= N1;
        if (j < N2) {
            int m = j / 192, k = j - m * 192;
            gw_proj[j] = __float2bfloat16(m < C_ ? wproj[m * 192 + k] : 0.f);
            continue;
        }
        j -= N2;
        if (j < N3) {
            int m = j / 192, k = j - m * 192;
            gw_in[j] = __float2bfloat16(m < HID2 ? win[m * 192 + k] : 0.f);
            continue;
        }
        j -= N3;
        if (j < N4) {
            int m = j / KPAD, k = j - m * KPAD;
            gw_out[j] = __float2bfloat16((m < C_ && k < HID) ? wout[m * HID + k] : 0.f);
            continue;
        }
        j -= N4;
        g_sumsq[j] = 0.f;
    }
}

// ---------------- channel LayerNorm: fp32 in -> bf16 out (2 pixels/thread) ----------------
__global__ __launch_bounds__(256) void ln_bf_kernel(const float* __restrict__ in,
                                                    const float* __restrict__ w,
                                                    const float* __restrict__ bias,
                                                    __nv_bfloat16* __restrict__ outp) {
    int idx = blockIdx.x * blockDim.x + threadIdx.x;  // 0 .. B*HW/2-1
    int b = idx >> 13;
    int p = (idx & 8191) * 2;
    const float* src = in + (size_t)b * C_ * HW + p;
    float s0 = 0.f, s1 = 0.f, q0 = 0.f, q1 = 0.f;
#pragma unroll 4
    for (int c = 0; c < C_; c++) {
        float2 v = *(const float2*)(src + (size_t)c * HW);
        s0 += v.x; q0 += v.x * v.x;
        s1 += v.y; q1 += v.y * v.y;
    }
    float mu0 = s0 * (1.0f / C_), mu1 = s1 * (1.0f / C_);
    float rs0 = rsqrtf(q0 * (1.0f / C_) - mu0 * mu0 + 1e-5f);
    float rs1 = rsqrtf(q1 * (1.0f / C_) - mu1 * mu1 + 1e-5f);
    __nv_bfloat16* dst = outp + (size_t)b * C_ * HW + p;
#pragma unroll 4
    for (int c = 0; c < C_; c++) {
        float2 v = *(const float2*)(src + (size_t)c * HW);
        float wc = w[c], bc = bias[c];
        __nv_bfloat162 h;
        h.x = __float2bfloat16((v.x - mu0) * rs0 * wc + bc);
        h.y = __float2bfloat16((v.y - mu1) * rs1 * wc + bc);
        *(__nv_bfloat162*)(dst + (size_t)c * HW) = h;
    }
}

// ---------------- bf16 tensor-core GEMM, cp.async double-buffered, ldmatrix ----------------
// Out[b][m][n] = sum_k A[m][k] * B[b][k][n];  A padded [Mp][K], B b-stride bStrideCh*HW
// mode 0: bf16 store to OutBf; 1: fp32 store acc+Res to OutF; 2: fp32 OutF += acc
#define BM 128
#define BN 128
#define BK 32
#define ASTR 40    // halves; 80B row stride -> conflict-free LDSM
#define BSTR 136   // halves; 272B row stride -> conflict-free LDSM.trans

__device__ __forceinline__ void cpa16(unsigned dst, const void* src) {
    asm volatile("cp.async.cg.shared.global [%0], [%1], 16;\n" :: "r"(dst), "l"(src));
}

__global__ __launch_bounds__(256) void gemm_bf(
    const __nv_bfloat16* __restrict__ A,
    const __nv_bfloat16* __restrict__ Bact, int bStrideCh,
    __nv_bfloat16* __restrict__ OutBf, int outStrideCh,
    float* __restrict__ OutF, const float* __restrict__ Res,
    int M, int K, int mode)
{
    __shared__ __align__(16) __nv_bfloat16 As[2][BM * ASTR];
    __shared__ __align__(16) __nv_bfloat16 Bs[2][BK * BSTR];

    const int b     = blockIdx.z;
    const int nBase = blockIdx.x * BN;
    const int mBase = blockIdx.y * BM;
    const int tid   = threadIdx.x;
    const int lane  = tid & 31, wid = tid >> 5;
    const int warpM = wid >> 2, warpN = wid & 3;   // 2 x 4 warps, warp tile 64x32
    const int g = lane >> 2, tig = lane & 3;

    const __nv_bfloat16* bsrc = Bact + (size_t)b * bStrideCh * HW;

    float acc[4][4][4];
#pragma unroll
    for (int i = 0; i < 4; i++)
#pragma unroll
        for (int j = 0; j < 4; j++)
#pragma unroll
            for (int r = 0; r < 4; r++) acc[i][j][r] = 0.f;

    const int nIter = K / BK;

    // ---- async stage loader: 2 x 16B for A, 2 x 16B for B per thread
    auto load_stage = [&](int s, int k0) {
        unsigned aBase = (unsigned)__cvta_generic_to_shared(&As[s][0]);
        unsigned bBase = (unsigned)__cvta_generic_to_shared(&Bs[s][0]);
#pragma unroll
        for (int u = 0; u < 2; u++) {
            int t  = tid * 2 + u;
            int ar = t >> 2, ac = (t & 3) * 8;
            cpa16(aBase + (unsigned)(ar * ASTR + ac) * 2u,
                  A + (size_t)(mBase + ar) * K + k0 + ac);
            int br = t >> 4, bc = (t & 15) * 8;
            cpa16(bBase + (unsigned)(br * BSTR + bc) * 2u,
                  bsrc + (size_t)(k0 + br) * HW + nBase + bc);
        }
    };

    load_stage(0, 0);
    asm volatile("cp.async.commit_group;\n");
    load_stage(1, BK);
    asm volatile("cp.async.commit_group;\n");

    // ldmatrix lane-address components
    const int aRowSel = ((lane >> 3) & 1) * 8 + (lane & 7);
    const int aKSel   = (lane >> 4) * 8;
    const int bKSel   = ((lane >> 3) & 1) * 8 + (lane & 7);
    const int bNSel   = (lane >> 4) * 8;

    for (int it = 0; it < nIter; it++) {
        asm volatile("cp.async.wait_group 1;\n");
        __syncthreads();
        const int s = it & 1;
        unsigned aB = (unsigned)__cvta_generic_to_shared(&As[s][0]);
        unsigned bB = (unsigned)__cvta_generic_to_shared(&Bs[s][0]);

#pragma unroll
        for (int ks = 0; ks < 2; ks++) {
            const int kb = ks * 16;
            unsigned af[4][4];
#pragma unroll
            for (int mt = 0; mt < 4; mt++) {
                int mloc = warpM * 64 + mt * 16 + aRowSel;
                unsigned addr = aB + (unsigned)(mloc * ASTR + kb + aKSel) * 2u;
                asm volatile("ldmatrix.sync.aligned.m8n8.x4.shared.b16 {%0,%1,%2,%3}, [%4];"
                             : "=r"(af[mt][0]), "=r"(af[mt][1]), "=r"(af[mt][2]), "=r"(af[mt][3])
                             : "r"(addr));
            }
            unsigned bfr[4][2];
#pragma unroll
            for (int half = 0; half < 2; half++) {
                int kloc = kb + bKSel;
                int nloc = warpN * 32 + half * 16 + bNSel;
                unsigned addr = bB + (unsigned)(kloc * BSTR + nloc) * 2u;
                unsigned r0, r1, r2, r3;
                asm volatile("ldmatrix.sync.aligned.m8n8.x4.trans.shared.b16 {%0,%1,%2,%3}, [%4];"
                             : "=r"(r0), "=r"(r1), "=r"(r2), "=r"(r3) : "r"(addr));
                bfr[half * 2 + 0][0] = r0; bfr[half * 2 + 0][1] = r1;
                bfr[half * 2 + 1][0] = r2; bfr[half * 2 + 1][1] = r3;
            }
#pragma unroll
            for (int mt = 0; mt < 4; mt++)
#pragma unroll
                for (int j = 0; j < 4; j++) {
                    asm volatile(
                        "mma.sync.aligned.m16n8k16.row.col.f32.bf16.bf16.f32 "
                        "{%0,%1,%2,%3}, {%4,%5,%6,%7}, {%8,%9}, {%0,%1,%2,%3};"
                        : "+f"(acc[mt][j][0]), "+f"(acc[mt][j][1]),
                          "+f"(acc[mt][j][2]), "+f"(acc[mt][j][3])
                        : "r"(af[mt][0]), "r"(af[mt][1]), "r"(af[mt][2]), "r"(af[mt][3]),
                          "r"(bfr[j][0]), "r"(bfr[j][1]));
                }
        }
        __syncthreads();
        int knext = (it + 2) * BK;
        if (knext < K) load_stage(s, knext);
        asm volatile("cp.async.commit_group;\n");
    }

    // ---- epilogue ----
#pragma unroll
    for (int mt = 0; mt < 4; mt++) {
        int mLo = mBase + warpM * 64 + mt * 16 + g;
        int mHi = mLo + 8;
#pragma unroll
        for (int j = 0; j < 4; j++) {
            int n = nBase + warpN * 32 + j * 8 + 2 * tig;
            if (mode == 0) {
                if (mLo < M) {
                    __nv_bfloat162 h;
                    h.x = __float2bfloat16(acc[mt][j][0]);
                    h.y = __float2bfloat16(acc[mt][j][1]);
                    *(__nv_bfloat162*)(OutBf + ((size_t)b * outStrideCh + mLo) * HW + n) = h;
                }
                if (mHi < M) {
                    __nv_bfloat162 h;
                    h.x = __float2bfloat16(acc[mt][j][2]);
                    h.y = __float2bfloat16(acc[mt][j][3]);
                    *(__nv_bfloat162*)(OutBf + ((size_t)b * outStrideCh + mHi) * HW + n) = h;
                }
            } else {
                if (mLo < M) {
                    size_t off = ((size_t)b * M + mLo) * HW + n;
                    float2 v = make_float2(acc[mt][j][0], acc[mt][j][1]);
                    if (mode == 1) { float2 r = *(const float2*)(Res + off); v.x += r.x; v.y += r.y; }
                    else           { float2 r = *(const float2*)(OutF + off); v.x += r.x; v.y += r.y; }
                    *(float2*)(OutF + off) = v;
                }
                if (mHi < M) {
                    size_t off = ((size_t)b * M + mHi) * HW + n;
                    float2 v = make_float2(acc[mt][j][2], acc[mt][j][3]);
                    if (mode == 1) { float2 r = *(const float2*)(Res + off); v.x += r.x; v.y += r.y; }
                    else           { float2 r = *(const float2*)(OutF + off); v.x += r.x; v.y += r.y; }
                    *(float2*)(OutF + off) = v;
                }
            }
        }
    }
}

// ---------------- depthwise 3x3 on qkv (bf16 in/out), 16-row tiles, + q/k sumsq ----------------
__global__ __launch_bounds__(256) void dwqkv_kernel(const float* __restrict__ wdw) {
    const int y0 = blockIdx.x * 16;
    const int c  = blockIdx.y;
    const int b  = blockIdx.z;
    const int tid = threadIdx.x;
    __shared__ float s[18][132];
    const __nv_bfloat16* src = gb_big + ((size_t)b * HID2 + c) * HW;
    for (int i = tid; i < 18 * 130; i += 256) {
        int r = i / 130, col = i - r * 130;
        int y = y0 + r - 1, x = col - 1;
        s[r][col] = (y >= 0 && y < H_ && x >= 0 && x < W_) ? __bfloat162float(src[y * W_ + x]) : 0.f;
    }
    __syncthreads();
    const float* wp = wdw + c * 9;
    const float w0 = wp[0], w1 = wp[1], w2 = wp[2], w3 = wp[3], w4 = wp[4],
                w5 = wp[5], w6 = wp[6], w7 = wp[7], w8 = wp[8];
    float sq = 0.f;
    __nv_bfloat16* dst = gb_qkv + ((size_t)b * C3 + c) * HW;
#pragma unroll
    for (int kk = 0; kk < 8; kk++) {
        int j = tid + kk * 256;
        int r = j >> 7, col = j & 127;
        float v = w0 * s[r    ][col] + w1 * s[r    ][col + 1] + w2 * s[r    ][col + 2]
                + w3 * s[r + 1][col] + w4 * s[r + 1][col + 1] + w5 * s[r + 1][col + 2]
                + w6 * s[r + 2][col] + w7 * s[r + 2][col + 1] + w8 * s[r + 2][col + 2];
        __nv_bfloat16 hb = __float2bfloat16(v);
        dst[(y0 + r) * W_ + col] = hb;
        float vb = __bfloat162float(hb);   // sumsq of the stored (bf16) value for consistency
        sq += vb * vb;
    }
    if (c < 2 * C_) {
#pragma unroll
        for (int o = 16; o; o >>= 1) sq += __shfl_xor_sync(0xffffffffu, sq, o);
        __shared__ float ws[8];
        if ((tid & 31) == 0) ws[tid >> 5] = sq;
        __syncthreads();
        if (tid == 0) {
            float t = 0.f;
#pragma unroll
            for (int i = 0; i < 8; i++) t += ws[i];
            atomicAdd(&g_sumsq[b * 2 * C_ + c], t);
        }
    }
}

// ---------------- attention scores + softmax: per (b, h, 4 d-rows) ----------------
__global__ __launch_bounds__(256) void attn_kernel(const float* __restrict__ temp) {
    int dg = blockIdx.x, h = blockIdx.y, b = blockIdx.z, tid = threadIdx.x;
    const __nv_bfloat16* base  = gb_qkv + (size_t)b * C3 * HW;
    const __nv_bfloat16* q0    = base + (size_t)(h * HD + dg * 4) * HW;
    const __nv_bfloat16* kbase = base + (size_t)(C_ + h * HD) * HW;

    float acc[4][24];
#pragma unroll
    for (int i = 0; i < 4; i++)
#pragma unroll
        for (int c = 0; c < 24; c++) acc[i][c] = 0.f;

    for (int p = 2 * tid; p < HW; p += 512) {
        float2 kv[24];
#pragma unroll
        for (int c = 0; c < 24; c++)
            kv[c] = __bfloat1622float2(*(const __nv_bfloat162*)(kbase + (size_t)c * HW + p));
#pragma unroll
        for (int i = 0; i < 4; i++) {
            float2 qv = __bfloat1622float2(*(const __nv_bfloat162*)(q0 + (size_t)i * HW + p));
#pragma unroll
            for (int c = 0; c < 24; c++)
                acc[i][c] += qv.x * kv[c].x + qv.y * kv[c].y;
        }
    }
#pragma unroll
    for (int i = 0; i < 4; i++)
#pragma unroll
        for (int c = 0; c < 24; c++)
#pragma unroll
            for (int o = 16; o; o >>= 1)
                acc[i][c] += __shfl_xor_sync(0xffffffffu, acc[i][c], o);

    __shared__ float red[8][96];
    __shared__ float S[96];
    int w = tid >> 5, lane = tid & 31;
    if (lane == 0) {
#pragma unroll
        for (int i = 0; i < 4; i++)
#pragma unroll
            for (int c = 0; c < 24; c++) red[w][i * 24 + c] = acc[i][c];
    }
    __syncthreads();
    if (tid < 96) {
        float s = 0.f;
#pragma unroll
        for (int ww = 0; ww < 8; ww++) s += red[ww][tid];
        S[tid] = s;
    }
    __syncthreads();

    if (tid < 4) {
        int d = dg * 4 + tid;
        float sq = g_sumsq[b * 2 * C_ + h * HD + d];
        float rq = 1.0f / fmaxf(sqrtf(sq), 1e-12f);
        float t  = temp[h];
        float row[24];
        float mx = -3.4e38f;
#pragma unroll
        for (int c = 0; c < 24; c++) {
            float sk = g_sumsq[b * 2 * C_ + C_ + h * HD + c];
            float rk = 1.0f / fmaxf(sqrtf(sk), 1e-12f);
            row[c] = S[tid * 24 + c] * rq * rk * t;
            mx = fmaxf(mx, row[c]);
        }
        float sum = 0.f;
#pragma unroll
        for (int c = 0; c < 24; c++) { row[c] = expf(row[c] - mx); sum += row[c]; }
        float inv = 1.0f / sum;
        float* ap = g_attn + (((size_t)(b * HEADS + h)) * HD + d) * HD;
#pragma unroll
        for (int c = 0; c < 24; c++) ap[c] = row[c] * inv;
    }
}

// ---------------- out = attn @ v -> gb_y (bf16), 2 pixels/thread ----------------
__global__ __launch_bounds__(256) void av_kernel() {
    int tid = threadIdx.x;
    int p = blockIdx.x * 512 + tid * 2;
    int h = blockIdx.y, b = blockIdx.z;
    __shared__ float A[HD * HD];
    const float* ap = g_attn + ((size_t)(b * HEADS + h)) * HD * HD;
    for (int i = tid; i < HD * HD; i += 256) A[i] = ap[i];
    __syncthreads();
    const __nv_bfloat16* vb = gb_qkv + (size_t)b * C3 * HW + (size_t)(2 * C_ + h * HD) * HW;
    float2 v[24];
#pragma unroll
    for (int c = 0; c < 24; c++)
        v[c] = __bfloat1622float2(*(const __nv_bfloat162*)(vb + (size_t)c * HW + p));
    __nv_bfloat16* ob = gb_y + (size_t)b * C_ * HW + (size_t)(h * HD) * HW;
#pragma unroll
    for (int d = 0; d < 24; d++) {
        float s0 = 0.f, s1 = 0.f;
#pragma unroll
        for (int c = 0; c < 24; c++) {
            float a = A[d * 24 + c];
            s0 += a * v[c].x;
            s1 += a * v[c].y;
        }
        __nv_bfloat162 hv;
        hv.x = __float2bfloat16(s0);
        hv.y = __float2bfloat16(s1);
        *(__nv_bfloat162*)(ob + (size_t)d * HW + p) = hv;
    }
}

// ---------------- FFN depthwise 3x3 + GELU gate (bf16 in/out), 16-row tiles ----------------
// grid.y = 512: j in [510,512) writes zeros (K padding for the last gemm)
__global__ __launch_bounds__(256) void dwgate_kernel(const float* __restrict__ wdw) {
    const int y0 = blockIdx.x * 16;
    const int j  = blockIdx.y;
    const int b  = blockIdx.z;
    const int tid = threadIdx.x;
    __nv_bfloat16* dst = gb_qkv + ((size_t)b * C3 + j) * HW;
    if (j >= HID) {   // zero pad channels (block-uniform branch)
#pragma unroll
        for (int kk = 0; kk < 8; kk++) {
            int jj = tid + kk * 256;
            int r = jj >> 7, col = jj & 127;
            dst[(y0 + r) * W_ + col] = __float2bfloat16(0.f);
        }
        return;
    }
    __shared__ float s1[18][132];
    __shared__ float s2[18][132];
    const __nv_bfloat16* src1 = gb_big + ((size_t)b * HID2 + j) * HW;
    const __nv_bfloat16* src2 = gb_big + ((size_t)b * HID2 + j + HID) * HW;
    for (int i = tid; i < 18 * 130; i += 256) {
        int r = i / 130, col = i - r * 130;
        int y = y0 + r - 1, x = col - 1;
        bool ok = (y >= 0 && y < H_ && x >= 0 && x < W_);
        s1[r][col] = ok ? __bfloat162float(src1[y * W_ + x]) : 0.f;
        s2[r][col] = ok ? __bfloat162float(src2[y * W_ + x]) : 0.f;
    }
    __syncthreads();
    const float* wa = wdw + j * 9;
    const float* wb = wdw + (j + HID) * 9;
    float a0 = wa[0], a1 = wa[1], a2 = wa[2], a3 = wa[3], a4 = wa[4],
          a5 = wa[5], a6 = wa[6], a7 = wa[7], a8 = wa[8];
    float b0 = wb[0], b1 = wb[1], b2 = wb[2], b3 = wb[3], b4 = wb[4],
          b5 = wb[5], b6 = wb[6], b7 = wb[7], b8 = wb[8];
#pragma unroll
    for (int kk = 0; kk < 8; kk++) {
        int jj = tid + kk * 256;
        int r = jj >> 7, col = jj & 127;
        float v1 = a0 * s1[r    ][col] + a1 * s1[r    ][col + 1] + a2 * s1[r    ][col + 2]
                 + a3 * s1[r + 1][col] + a4 * s1[r + 1][col + 1] + a5 * s1[r + 1][col + 2]
                 + a6 * s1[r + 2][col] + a7 * s1[r + 2][col + 1] + a8 * s1[r + 2][col + 2];
        float v2 = b0 * s2[r    ][col] + b1 * s2[r    ][col + 1] + b2 * s2[r    ][col + 2]
                 + b3 * s2[r + 1][col] + b4 * s2[r + 1][col + 1] + b5 * s2[r + 1][col + 2]
                 + b6 * s2[r + 2][col] + b7 * s2[r + 2][col + 1] + b8 * s2[r + 2][col + 2];
        float gl = 0.5f * v1 * (1.0f + erff(v1 * 0.70710678118654752440f));
        dst[(y0 + r) * W_ + col] = __float2bfloat16(gl * v2);
    }
}

// ---------------- launch ----------------
extern "C" void kernel_launch(void* const* d_in, const int* in_sizes, int n_in,
                              void* d_out, int out_size) {
    const float* x      = (const float*)d_in[0];
    const float* temp   = (const float*)d_in[1];
    const float* ln1w   = (const float*)d_in[2];
    const float* ln1b   = (const float*)d_in[3];
    const float* ln2w   = (const float*)d_in[4];
    const float* ln2b   = (const float*)d_in[5];
    const float* wqkv   = (const float*)d_in[6];
    const float* wqkvdw = (const float*)d_in[7];
    const float* wproj  = (const float*)d_in[8];
    const float* win    = (const float*)d_in[9];
    const float* wdw    = (const float*)d_in[10];
    const float* wout   = (const float*)d_in[11];
    float* out = (float*)d_out;

    __nv_bfloat16 *pBig, *pQkv, *pY, *pWqkv, *pWproj, *pWin, *pWout;
    cudaGetSymbolAddress((void**)&pBig,  gb_big);
    cudaGetSymbolAddress((void**)&pQkv,  gb_qkv);
    cudaGetSymbolAddress((void**)&pY,    gb_y);
    cudaGetSymbolAddress((void**)&pWqkv, gw_qkv);
    cudaGetSymbolAddress((void**)&pWproj,gw_proj);
    cudaGetSymbolAddress((void**)&pWin,  gw_in);
    cudaGetSymbolAddress((void**)&pWout, gw_out);

    prep_kernel<<<512, 256>>>(wqkv, wproj, win, wout);

    // --- attention branch ---
    ln_bf_kernel<<<(B_ * HW / 2) / 256, 256>>>(x, ln1w, ln1b, pY);
    gemm_bf<<<dim3(128, 5, B_), 256>>>(pWqkv, pY, C_, pBig, HID2, nullptr, nullptr, C3, 192, 0);
    dwqkv_kernel<<<dim3(8, C3, B_), 256>>>(wqkvdw);
    attn_kernel<<<dim3(HD / 4, HEADS, B_), 256>>>(temp);
    av_kernel<<<dim3(HW / 512, HEADS, B_), 256>>>();
    gemm_bf<<<dim3(128, 2, B_), 256>>>(pWproj, pY, C_, nullptr, 0, out, x, C_, 192, 1);

    // --- FFN branch ---
    ln_bf_kernel<<<(B_ * HW / 2) / 256, 256>>>(out, ln2w, ln2b, pY);
    gemm_bf<<<dim3(128, 8, B_), 256>>>(pWin, pY, C_, pBig, HID2, nullptr, nullptr, HID2, 192, 0);
    dwgate_kernel<<<dim3(8, KPAD, B_), 256>>>(wdw);
    gemm_bf<<<dim3(128, 2, B_), 256>>>(pWout, pQkv, C3, nullptr, 0, out, nullptr, C_, KPAD, 2);
}

// round 7
// speedup vs baseline: 3.5914x; 1.1260x over previous
#include <cuda_runtime.h>
#include <cuda_bf16.h>
#include <stdint.h>
#include <math.h>

#define B_    4
#define C_    192
#define H_    128
#define W_    128
#define HW    16384
#define HEADS 8
#define HD    24
#define C3    576
#define HID   510
#define HID2  1020
#define KPAD  512

// ---------------- scratch (device globals; no allocs) ----------------
__device__ __nv_bfloat16 gb_big[(size_t)B_ * HID2 * HW];
__device__ __nv_bfloat16 gb_qkv[(size_t)B_ * C3 * HW];
__device__ __nv_bfloat16 gb_y  [(size_t)B_ * C_ * HW];
__device__ float g_sumsq[B_ * 2 * C_];
__device__ float g_attn [B_ * HEADS * HD * HD];
__device__ __nv_bfloat16 gw_qkv[640 * 192];
__device__ __nv_bfloat16 gw_proj[256 * 192];
__device__ __nv_bfloat16 gw_in [1024 * 192];
__device__ __nv_bfloat16 gw_out[256 * KPAD];

__device__ __forceinline__ unsigned bf2u(__nv_bfloat162 h) { return *(unsigned*)&h; }

// ---------------- prep: convert/pad weights, zero sumsq + attn ----------------
__global__ void prep_kernel(const float* __restrict__ wqkv, const float* __restrict__ wproj,
                            const float* __restrict__ win,  const float* __restrict__ wout) {
    const int N1 = 640 * 192, N2 = 256 * 192, N3 = 1024 * 192, N4 = 256 * KPAD;
    const int N5 = B_ * 2 * C_, N6 = B_ * HEADS * HD * HD;
    const int TOT = N1 + N2 + N3 + N4 + N5 + N6;
    for (int i = blockIdx.x * blockDim.x + threadIdx.x; i < TOT; i += gridDim.x * blockDim.x) {
        int j = i;
        if (j < N1) { int m = j / 192, k = j - m * 192;
            gw_qkv[j] = __float2bfloat16(m < C3 ? wqkv[m * 192 + k] : 0.f); continue; }
        j -= N1;
        if (j < N2) { int m = j / 192, k = j - m * 192;
            gw_proj[j] = __float2bfloat16(m < C_ ? wproj[m * 192 + k] : 0.f); continue; }
        j -= N2;
        if (j < N3) { int m = j / 192, k = j - m * 192;
            gw_in[j] = __float2bfloat16(m < HID2 ? win[m * 192 + k] : 0.f); continue; }
        j -= N3;
        if (j < N4) { int m = j / KPAD, k = j - m * KPAD;
            gw_out[j] = __float2bfloat16((m < C_ && k < HID) ? wout[m * HID + k] : 0.f); continue; }
        j -= N4;
        if (j < N5) { g_sumsq[j] = 0.f; continue; }
        j -= N5;
        g_attn[j] = 0.f;
    }
}

// ---------------- channel LayerNorm: fp32 in -> bf16 out (4 pixels/thread) ----------------
__global__ __launch_bounds__(256) void ln_bf_kernel(const float* __restrict__ in,
                                                    const float* __restrict__ w,
                                                    const float* __restrict__ bias,
                                                    __nv_bfloat16* __restrict__ outp) {
    int idx = blockIdx.x * blockDim.x + threadIdx.x;   // 0 .. B*HW/4-1
    int b = idx >> 12;
    int p = (idx & 4095) << 2;
    const float* src = in + (size_t)b * C_ * HW + p;
    float4 s = make_float4(0.f, 0.f, 0.f, 0.f);
    float4 q = make_float4(0.f, 0.f, 0.f, 0.f);
#pragma unroll 8
    for (int c = 0; c < C_; c++) {
        float4 v = *(const float4*)(src + (size_t)c * HW);
        s.x += v.x; s.y += v.y; s.z += v.z; s.w += v.w;
        q.x += v.x * v.x; q.y += v.y * v.y; q.z += v.z * v.z; q.w += v.w * v.w;
    }
    const float ic = 1.0f / C_;
    float4 mu = make_float4(s.x * ic, s.y * ic, s.z * ic, s.w * ic);
    float4 rs;
    rs.x = rsqrtf(q.x * ic - mu.x * mu.x + 1e-5f);
    rs.y = rsqrtf(q.y * ic - mu.y * mu.y + 1e-5f);
    rs.z = rsqrtf(q.z * ic - mu.z * mu.z + 1e-5f);
    rs.w = rsqrtf(q.w * ic - mu.w * mu.w + 1e-5f);
    __nv_bfloat16* dst = outp + (size_t)b * C_ * HW + p;
#pragma unroll 8
    for (int c = 0; c < C_; c++) {
        float4 v = *(const float4*)(src + (size_t)c * HW);
        float wc = w[c], bc = bias[c];
        __nv_bfloat162 h0, h1;
        h0.x = __float2bfloat16((v.x - mu.x) * rs.x * wc + bc);
        h0.y = __float2bfloat16((v.y - mu.y) * rs.y * wc + bc);
        h1.x = __float2bfloat16((v.z - mu.z) * rs.z * wc + bc);
        h1.y = __float2bfloat16((v.w - mu.w) * rs.w * wc + bc);
        uint2 u; u.x = bf2u(h0); u.y = bf2u(h1);
        *(uint2*)(dst + (size_t)c * HW) = u;
    }
}

// ---------------- bf16 tensor-core GEMM (templated K/mode) ----------------
#define BM 128
#define BN 128
#define BK 32
#define ASTR 40
#define BSTR 136

__device__ __forceinline__ void cpa16(unsigned dst, const void* src) {
    asm volatile("cp.async.cg.shared.global [%0], [%1], 16;\n" :: "r"(dst), "l"(src));
}

template<int K, int MODE>
__global__ __launch_bounds__(256) void gemm_bf(
    const __nv_bfloat16* __restrict__ A,
    const __nv_bfloat16* __restrict__ Bact, int bStrideCh,
    __nv_bfloat16* __restrict__ OutBf, int outStrideCh,
    float* __restrict__ OutF, const float* __restrict__ Res, int M)
{
    __shared__ __align__(16) __nv_bfloat16 As[2][BM * ASTR];
    __shared__ __align__(16) __nv_bfloat16 Bs[2][BK * BSTR];

    const int b     = blockIdx.z;
    const int nBase = blockIdx.x * BN;
    const int mBase = blockIdx.y * BM;
    const int tid   = threadIdx.x;
    const int lane  = tid & 31, wid = tid >> 5;
    const int warpM = wid >> 2, warpN = wid & 3;
    const int g = lane >> 2, tig = lane & 3;

    const __nv_bfloat16* bsrc = Bact + (size_t)b * bStrideCh * HW;

    float acc[4][4][4];
#pragma unroll
    for (int i = 0; i < 4; i++)
#pragma unroll
        for (int j = 0; j < 4; j++)
#pragma unroll
            for (int r = 0; r < 4; r++) acc[i][j][r] = 0.f;

    constexpr int nIter = K / BK;

    auto load_stage = [&](int s, int k0) {
        unsigned aBase = (unsigned)__cvta_generic_to_shared(&As[s][0]);
        unsigned bBase = (unsigned)__cvta_generic_to_shared(&Bs[s][0]);
#pragma unroll
        for (int u = 0; u < 2; u++) {
            int t  = tid * 2 + u;
            int ar = t >> 2, ac = (t & 3) * 8;
            cpa16(aBase + (unsigned)(ar * ASTR + ac) * 2u,
                  A + (size_t)(mBase + ar) * K + k0 + ac);
            int br = t >> 4, bc = (t & 15) * 8;
            cpa16(bBase + (unsigned)(br * BSTR + bc) * 2u,
                  bsrc + (size_t)(k0 + br) * HW + nBase + bc);
        }
    };

    load_stage(0, 0);
    asm volatile("cp.async.commit_group;\n");
    load_stage(1, BK);
    asm volatile("cp.async.commit_group;\n");

    const int aRowSel = ((lane >> 3) & 1) * 8 + (lane & 7);
    const int aKSel   = (lane >> 4) * 8;
    const int bKSel   = ((lane >> 3) & 1) * 8 + (lane & 7);
    const int bNSel   = (lane >> 4) * 8;

#pragma unroll 2
    for (int it = 0; it < nIter; it++) {
        asm volatile("cp.async.wait_group 1;\n");
        __syncthreads();
        const int s = it & 1;
        unsigned aB = (unsigned)__cvta_generic_to_shared(&As[s][0]);
        unsigned bB = (unsigned)__cvta_generic_to_shared(&Bs[s][0]);

#pragma unroll
        for (int ks = 0; ks < 2; ks++) {
            const int kb = ks * 16;
            unsigned af[4][4];
#pragma unroll
            for (int mt = 0; mt < 4; mt++) {
                int mloc = warpM * 64 + mt * 16 + aRowSel;
                unsigned addr = aB + (unsigned)(mloc * ASTR + kb + aKSel) * 2u;
                asm volatile("ldmatrix.sync.aligned.m8n8.x4.shared.b16 {%0,%1,%2,%3}, [%4];"
                             : "=r"(af[mt][0]), "=r"(af[mt][1]), "=r"(af[mt][2]), "=r"(af[mt][3])
                             : "r"(addr));
            }
            unsigned bfr[4][2];
#pragma unroll
            for (int half = 0; half < 2; half++) {
                int kloc = kb + bKSel;
                int nloc = warpN * 32 + half * 16 + bNSel;
                unsigned addr = bB + (unsigned)(kloc * BSTR + nloc) * 2u;
                unsigned r0, r1, r2, r3;
                asm volatile("ldmatrix.sync.aligned.m8n8.x4.trans.shared.b16 {%0,%1,%2,%3}, [%4];"
                             : "=r"(r0), "=r"(r1), "=r"(r2), "=r"(r3) : "r"(addr));
                bfr[half * 2 + 0][0] = r0; bfr[half * 2 + 0][1] = r1;
                bfr[half * 2 + 1][0] = r2; bfr[half * 2 + 1][1] = r3;
            }
#pragma unroll
            for (int mt = 0; mt < 4; mt++)
#pragma unroll
                for (int j = 0; j < 4; j++) {
                    asm volatile(
                        "mma.sync.aligned.m16n8k16.row.col.f32.bf16.bf16.f32 "
                        "{%0,%1,%2,%3}, {%4,%5,%6,%7}, {%8,%9}, {%0,%1,%2,%3};"
                        : "+f"(acc[mt][j][0]), "+f"(acc[mt][j][1]),
                          "+f"(acc[mt][j][2]), "+f"(acc[mt][j][3])
                        : "r"(af[mt][0]), "r"(af[mt][1]), "r"(af[mt][2]), "r"(af[mt][3]),
                          "r"(bfr[j][0]), "r"(bfr[j][1]));
                }
        }
        __syncthreads();
        int knext = (it + 2) * BK;
        if (knext < K) load_stage(s, knext);
        asm volatile("cp.async.commit_group;\n");
    }

#pragma unroll
    for (int mt = 0; mt < 4; mt++) {
        int mLo = mBase + warpM * 64 + mt * 16 + g;
        int mHi = mLo + 8;
#pragma unroll
        for (int j = 0; j < 4; j++) {
            int n = nBase + warpN * 32 + j * 8 + 2 * tig;
            if (MODE == 0) {
                if (mLo < M) {
                    __nv_bfloat162 h;
                    h.x = __float2bfloat16(acc[mt][j][0]);
                    h.y = __float2bfloat16(acc[mt][j][1]);
                    *(__nv_bfloat162*)(OutBf + ((size_t)b * outStrideCh + mLo) * HW + n) = h;
                }
                if (mHi < M) {
                    __nv_bfloat162 h;
                    h.x = __float2bfloat16(acc[mt][j][2]);
                    h.y = __float2bfloat16(acc[mt][j][3]);
                    *(__nv_bfloat162*)(OutBf + ((size_t)b * outStrideCh + mHi) * HW + n) = h;
                }
            } else {
                if (mLo < M) {
                    size_t off = ((size_t)b * M + mLo) * HW + n;
                    float2 v = make_float2(acc[mt][j][0], acc[mt][j][1]);
                    if (MODE == 1) { float2 r = *(const float2*)(Res + off); v.x += r.x; v.y += r.y; }
                    else           { float2 r = *(const float2*)(OutF + off); v.x += r.x; v.y += r.y; }
                    *(float2*)(OutF + off) = v;
                }
                if (mHi < M) {
                    size_t off = ((size_t)b * M + mHi) * HW + n;
                    float2 v = make_float2(acc[mt][j][2], acc[mt][j][3]);
                    if (MODE == 1) { float2 r = *(const float2*)(Res + off); v.x += r.x; v.y += r.y; }
                    else           { float2 r = *(const float2*)(OutF + off); v.x += r.x; v.y += r.y; }
                    *(float2*)(OutF + off) = v;
                }
            }
        }
    }
}

// ---------------- helper: fill one smem halo tile from bf16 source ----------------
__device__ __forceinline__ void fill_tile(float (*s)[132], const __nv_bfloat16* src,
                                          int y0, int tid) {
    for (int i = tid; i < 288; i += 256) {
        int r = i >> 4, cc = i & 15;
        int y = y0 + r - 1;
        float f[8];
        if (y >= 0 && y < H_) {
            uint4 u = *(const uint4*)(src + y * W_ + cc * 8);
            __nv_bfloat162* hp = (__nv_bfloat162*)&u;
            float2 a = __bfloat1622float2(hp[0]);
            float2 bb = __bfloat1622float2(hp[1]);
            float2 cc2 = __bfloat1622float2(hp[2]);
            float2 d = __bfloat1622float2(hp[3]);
            f[0] = a.x; f[1] = a.y; f[2] = bb.x; f[3] = bb.y;
            f[4] = cc2.x; f[5] = cc2.y; f[6] = d.x; f[7] = d.y;
        } else {
#pragma unroll
            for (int t = 0; t < 8; t++) f[t] = 0.f;
        }
#pragma unroll
        for (int t = 0; t < 8; t++) s[r][1 + cc * 8 + t] = f[t];
    }
}

// ---------------- depthwise 3x3 qkv (vectorized) + q/k sumsq ----------------
__global__ __launch_bounds__(256) void dwqkv_kernel(const float* __restrict__ wdw) {
    const int y0 = blockIdx.x * 16, c = blockIdx.y, b = blockIdx.z, tid = threadIdx.x;
    __shared__ float s[18][132];
    if (tid < 36) { int r = tid >> 1; s[r][(tid & 1) ? 129 : 0] = 0.f; }
    const __nv_bfloat16* src = gb_big + ((size_t)b * HID2 + c) * HW;
    fill_tile(s, src, y0, tid);
    __syncthreads();
    const float* wp = wdw + c * 9;
    const float w0 = wp[0], w1 = wp[1], w2 = wp[2], w3 = wp[3], w4 = wp[4],
                w5 = wp[5], w6 = wp[6], w7 = wp[7], w8 = wp[8];
    const int r = tid >> 4, c0 = (tid & 15) * 8;
    float row[3][10];
#pragma unroll
    for (int rr = 0; rr < 3; rr++) {
        float4 p0 = *(const float4*)&s[r + rr][c0];
        float4 p1 = *(const float4*)&s[r + rr][c0 + 4];
        float2 p2 = *(const float2*)&s[r + rr][c0 + 8];
        row[rr][0] = p0.x; row[rr][1] = p0.y; row[rr][2] = p0.z; row[rr][3] = p0.w;
        row[rr][4] = p1.x; row[rr][5] = p1.y; row[rr][6] = p1.z; row[rr][7] = p1.w;
        row[rr][8] = p2.x; row[rr][9] = p2.y;
    }
    float sq = 0.f;
    __nv_bfloat162 o[4];
#pragma unroll
    for (int x = 0; x < 8; x++) {
        float v = w0 * row[0][x] + w1 * row[0][x + 1] + w2 * row[0][x + 2]
                + w3 * row[1][x] + w4 * row[1][x + 1] + w5 * row[1][x + 2]
                + w6 * row[2][x] + w7 * row[2][x + 1] + w8 * row[2][x + 2];
        __nv_bfloat16 hb = __float2bfloat16(v);
        float vb = __bfloat162float(hb);
        sq += vb * vb;
        if (x & 1) o[x >> 1].y = hb; else o[x >> 1].x = hb;
    }
    __nv_bfloat16* dst = gb_qkv + ((size_t)b * C3 + c) * HW;
    uint4 pack;
    pack.x = bf2u(o[0]); pack.y = bf2u(o[1]); pack.z = bf2u(o[2]); pack.w = bf2u(o[3]);
    *(uint4*)(dst + (y0 + r) * W_ + c0) = pack;

    if (c < 2 * C_) {
#pragma unroll
        for (int off = 16; off; off >>= 1) sq += __shfl_xor_sync(0xffffffffu, sq, off);
        __shared__ float ws[8];
        if ((tid & 31) == 0) ws[tid >> 5] = sq;
        __syncthreads();
        if (tid == 0) {
            float t = 0.f;
#pragma unroll
            for (int i = 0; i < 8; i++) t += ws[i];
            atomicAdd(&g_sumsq[b * 2 * C_ + c], t);
        }
    }
}

// ---------------- attention partial scores: smem-staged, p-split, atomics ----------------
#define PSPLIT 8
__global__ __launch_bounds__(256) void attn_part_kernel() {
    const int ps = blockIdx.x, h = blockIdx.y, b = blockIdx.z;
    const int tid = threadIdx.x, warp = tid >> 5, lane = tid & 31;
    const __nv_bfloat16* base = gb_qkv + (size_t)b * C3 * HW;
    const __nv_bfloat16* qb = base + (size_t)(h * HD) * HW;
    const __nv_bfloat16* kb = base + (size_t)(C_ + h * HD) * HW;
    __shared__ float qs[24][132];
    __shared__ float ks[24][132];

    float acc[3][24];
#pragma unroll
    for (int r = 0; r < 3; r++)
#pragma unroll
        for (int c = 0; c < 24; c++) acc[r][c] = 0.f;

    const int p0 = ps * (HW / PSPLIT);
    for (int t = 0; t < (HW / PSPLIT) / 128; t++) {
        int pt = p0 + t * 128;
        __syncthreads();
        for (int i = tid; i < 768; i += 256) {
            int ch = i >> 5, seg = (i & 31) * 4;
            uint2 u = *(const uint2*)(kb + (size_t)ch * HW + pt + seg);
            float2 f0 = __bfloat1622float2(*(__nv_bfloat162*)&u.x);
            float2 f1 = __bfloat1622float2(*(__nv_bfloat162*)&u.y);
            *(float4*)&ks[ch][seg] = make_float4(f0.x, f0.y, f1.x, f1.y);
            uint2 v = *(const uint2*)(qb + (size_t)ch * HW + pt + seg);
            float2 g0 = __bfloat1622float2(*(__nv_bfloat162*)&v.x);
            float2 g1 = __bfloat1622float2(*(__nv_bfloat162*)&v.y);
            *(float4*)&qs[ch][seg] = make_float4(g0.x, g0.y, g1.x, g1.y);
        }
        __syncthreads();
        float4 qv[3];
#pragma unroll
        for (int r = 0; r < 3; r++)
            qv[r] = *(const float4*)&qs[warp * 3 + r][lane * 4];
#pragma unroll
        for (int ch = 0; ch < 24; ch++) {
            float4 kv = *(const float4*)&ks[ch][lane * 4];
#pragma unroll
            for (int r = 0; r < 3; r++)
                acc[r][ch] += qv[r].x * kv.x + qv[r].y * kv.y + qv[r].z * kv.z + qv[r].w * kv.w;
        }
    }
#pragma unroll
    for (int r = 0; r < 3; r++)
#pragma unroll
        for (int c = 0; c < 24; c++)
#pragma unroll
            for (int off = 16; off; off >>= 1)
                acc[r][c] += __shfl_xor_sync(0xffffffffu, acc[r][c], off);
    if (lane == 0) {
        float* ap = g_attn + (((size_t)(b * HEADS + h)) * HD + warp * 3) * HD;
#pragma unroll
        for (int r = 0; r < 3; r++)
#pragma unroll
            for (int c = 0; c < 24; c++)
                atomicAdd(&ap[r * HD + c], acc[r][c]);
    }
}

// ---------------- softmax finalize (l2norm scaling + temperature) ----------------
__global__ void softmax_kernel(const float* __restrict__ temp) {
    int i = blockIdx.x * blockDim.x + threadIdx.x;   // (b*HEADS+h)*HD + d
    if (i >= B_ * HEADS * HD) return;
    int d = i % HD;
    int bh = i / HD;
    int h = bh % HEADS, b = bh / HEADS;
    float* rowp = g_attn + (size_t)i * HD;
    float sq = g_sumsq[b * 2 * C_ + h * HD + d];
    float rq = 1.0f / fmaxf(sqrtf(sq), 1e-12f);
    float t = temp[h];
    float row[24];
    float mx = -3.4e38f;
#pragma unroll
    for (int c = 0; c < 24; c++) {
        float sk = g_sumsq[b * 2 * C_ + C_ + h * HD + c];
        float rk = 1.0f / fmaxf(sqrtf(sk), 1e-12f);
        row[c] = rowp[c] * rq * rk * t;
        mx = fmaxf(mx, row[c]);
    }
    float sum = 0.f;
#pragma unroll
    for (int c = 0; c < 24; c++) { row[c] = expf(row[c] - mx); sum += row[c]; }
    float inv = 1.0f / sum;
#pragma unroll
    for (int c = 0; c < 24; c++) rowp[c] = row[c] * inv;
}

// ---------------- out = attn @ v -> gb_y (bf16), 4 pixels/thread ----------------
__global__ __launch_bounds__(256) void av_kernel() {
    int tid = threadIdx.x;
    int p = blockIdx.x * 1024 + tid * 4;
    int h = blockIdx.y, b = blockIdx.z;
    __shared__ float A[HD * HD];
    const float* ap = g_attn + ((size_t)(b * HEADS + h)) * HD * HD;
    for (int i = tid; i < HD * HD; i += 256) A[i] = ap[i];
    __syncthreads();
    const __nv_bfloat16* vb = gb_qkv + (size_t)b * C3 * HW + (size_t)(2 * C_ + h * HD) * HW;
    float4 v[24];
#pragma unroll
    for (int c = 0; c < 24; c++) {
        uint2 u = *(const uint2*)(vb + (size_t)c * HW + p);
        float2 f0 = __bfloat1622float2(*(__nv_bfloat162*)&u.x);
        float2 f1 = __bfloat1622float2(*(__nv_bfloat162*)&u.y);
        v[c] = make_float4(f0.x, f0.y, f1.x, f1.y);
    }
    __nv_bfloat16* ob = gb_y + (size_t)b * C_ * HW + (size_t)(h * HD) * HW;
#pragma unroll
    for (int d = 0; d < 24; d++) {
        float s0 = 0.f, s1 = 0.f, s2 = 0.f, s3 = 0.f;
#pragma unroll
        for (int c = 0; c < 24; c++) {
            float a = A[d * 24 + c];
            s0 += a * v[c].x; s1 += a * v[c].y; s2 += a * v[c].z; s3 += a * v[c].w;
        }
        __nv_bfloat162 h0, h1;
        h0.x = __float2bfloat16(s0); h0.y = __float2bfloat16(s1);
        h1.x = __float2bfloat16(s2); h1.y = __float2bfloat16(s3);
        uint2 u; u.x = bf2u(h0); u.y = bf2u(h1);
        *(uint2*)(ob + (size_t)d * HW + p) = u;
    }
}

// ---------------- FFN depthwise 3x3 + GELU gate (vectorized) ----------------
__global__ __launch_bounds__(256) void dwgate_kernel(const float* __restrict__ wdw) {
    const int y0 = blockIdx.x * 16, j = blockIdx.y, b = blockIdx.z, tid = threadIdx.x;
    __nv_bfloat16* dst = gb_qkv + ((size_t)b * C3 + j) * HW;
    if (j >= HID) {    // K-pad channels -> zeros (uniform branch)
        int r = tid >> 4, c0 = (tid & 15) * 8;
        uint4 z = make_uint4(0u, 0u, 0u, 0u);
        *(uint4*)(dst + (y0 + r) * W_ + c0) = z;
        return;
    }
    __shared__ float s1[18][132];
    __shared__ float s2[18][132];
    if (tid < 72) {
        int k = tid >> 2, which = (tid >> 1) & 1, side = tid & 1;
        float* arr = which ? &s2[k][0] : &s1[k][0];
        arr[side ? 129 : 0] = 0.f;
    }
    const __nv_bfloat16* src1 = gb_big + ((size_t)b * HID2 + j) * HW;
    const __nv_bfloat16* src2 = gb_big + ((size_t)b * HID2 + j + HID) * HW;
    fill_tile(s1, src1, y0, tid);
    fill_tile(s2, src2, y0, tid);
    __syncthreads();
    const float* wa = wdw + j * 9;
    const float* wb = wdw + (j + HID) * 9;
    const float a0 = wa[0], a1 = wa[1], a2 = wa[2], a3 = wa[3], a4 = wa[4],
                a5 = wa[5], a6 = wa[6], a7 = wa[7], a8 = wa[8];
    const float b0 = wb[0], b1 = wb[1], b2 = wb[2], b3 = wb[3], b4 = wb[4],
                b5 = wb[5], b6 = wb[6], b7 = wb[7], b8 = wb[8];
    const int r = tid >> 4, c0 = (tid & 15) * 8;
    float r1[3][10], r2[3][10];
#pragma unroll
    for (int rr = 0; rr < 3; rr++) {
        float4 p0 = *(const float4*)&s1[r + rr][c0];
        float4 p1 = *(const float4*)&s1[r + rr][c0 + 4];
        float2 p2 = *(const float2*)&s1[r + rr][c0 + 8];
        r1[rr][0] = p0.x; r1[rr][1] = p0.y; r1[rr][2] = p0.z; r1[rr][3] = p0.w;
        r1[rr][4] = p1.x; r1[rr][5] = p1.y; r1[rr][6] = p1.z; r1[rr][7] = p1.w;
        r1[rr][8] = p2.x; r1[rr][9] = p2.y;
        float4 q0 = *(const float4*)&s2[r + rr][c0];
        float4 q1 = *(const float4*)&s2[r + rr][c0 + 4];
        float2 q2 = *(const float2*)&s2[r + rr][c0 + 8];
        r2[rr][0] = q0.x; r2[rr][1] = q0.y; r2[rr][2] = q0.z; r2[rr][3] = q0.w;
        r2[rr][4] = q1.x; r2[rr][5] = q1.y; r2[rr][6] = q1.z; r2[rr][7] = q1.w;
        r2[rr][8] = q2.x; r2[rr][9] = q2.y;
    }
    __nv_bfloat162 o[4];
#pragma unroll
    for (int x = 0; x < 8; x++) {
        float v1 = a0 * r1[0][x] + a1 * r1[0][x + 1] + a2 * r1[0][x + 2]
                 + a3 * r1[1][x] + a4 * r1[1][x + 1] + a5 * r1[1][x + 2]
                 + a6 * r1[2][x] + a7 * r1[2][x + 1] + a8 * r1[2][x + 2];
        float v2 = b0 * r2[0][x] + b1 * r2[0][x + 1] + b2 * r2[0][x + 2]
                 + b3 * r2[1][x] + b4 * r2[1][x + 1] + b5 * r2[1][x + 2]
                 + b6 * r2[2][x] + b7 * r2[2][x + 1] + b8 * r2[2][x + 2];
        float gl = 0.5f * v1 * (1.0f + erff(v1 * 0.70710678118654752440f));
        __nv_bfloat16 hb = __float2bfloat16(gl * v2);
        if (x & 1) o[x >> 1].y = hb; else o[x >> 1].x = hb;
    }
    uint4 pack;
    pack.x = bf2u(o[0]); pack.y = bf2u(o[1]); pack.z = bf2u(o[2]); pack.w = bf2u(o[3]);
    *(uint4*)(dst + (y0 + r) * W_ + c0) = pack;
}

// ---------------- launch ----------------
extern "C" void kernel_launch(void* const* d_in, const int* in_sizes, int n_in,
                              void* d_out, int out_size) {
    const float* x      = (const float*)d_in[0];
    const float* temp   = (const float*)d_in[1];
    const float* ln1w   = (const float*)d_in[2];
    const float* ln1b   = (const float*)d_in[3];
    const float* ln2w   = (const float*)d_in[4];
    const float* ln2b   = (const float*)d_in[5];
    const float* wqkv   = (const float*)d_in[6];
    const float* wqkvdw = (const float*)d_in[7];
    const float* wproj  = (const float*)d_in[8];
    const float* win    = (const float*)d_in[9];
    const float* wdw    = (const float*)d_in[10];
    const float* wout   = (const float*)d_in[11];
    float* out = (float*)d_out;

    __nv_bfloat16 *pBig, *pQkv, *pY, *pWqkv, *pWproj, *pWin, *pWout;
    cudaGetSymbolAddress((void**)&pBig,  gb_big);
    cudaGetSymbolAddress((void**)&pQkv,  gb_qkv);
    cudaGetSymbolAddress((void**)&pY,    gb_y);
    cudaGetSymbolAddress((void**)&pWqkv, gw_qkv);
    cudaGetSymbolAddress((void**)&pWproj,gw_proj);
    cudaGetSymbolAddress((void**)&pWin,  gw_in);
    cudaGetSymbolAddress((void**)&pWout, gw_out);

    prep_kernel<<<512, 256>>>(wqkv, wproj, win, wout);

    // --- attention branch ---
    ln_bf_kernel<<<(B_ * HW / 4) / 256, 256>>>(x, ln1w, ln1b, pY);
    gemm_bf<192, 0><<<dim3(128, 5, B_), 256>>>(pWqkv, pY, C_, pBig, HID2, nullptr, nullptr, C3);
    dwqkv_kernel<<<dim3(8, C3, B_), 256>>>(wqkvdw);
    attn_part_kernel<<<dim3(PSPLIT, HEADS, B_), 256>>>();
    softmax_kernel<<<3, 256>>>(temp);
    av_kernel<<<dim3(HW / 1024, HEADS, B_), 256>>>();
    gemm_bf<192, 1><<<dim3(128, 2, B_), 256>>>(pWproj, pY, C_, nullptr, 0, out, x, C_);

    // --- FFN branch ---
    ln_bf_kernel<<<(B_ * HW / 4) / 256, 256>>>(out, ln2w, ln2b, pY);
    gemm_bf<192, 0><<<dim3(128, 8, B_), 256>>>(pWin, pY, C_, pBig, HID2, nullptr, nullptr, HID2);
    dwgate_kernel<<<dim3(8, KPAD, B_), 256>>>(wdw);
    gemm_bf<512, 2><<<dim3(128, 2, B_), 256>>>(pWout, pQkv, C3, nullptr, 0, out, nullptr, C_);
}

// round 8
// speedup vs baseline: 3.6193x; 1.0078x over previous
#include <cuda_runtime.h>
#include <cuda_bf16.h>
#include <stdint.h>
#include <math.h>

#define B_    4
#define C_    192
#define H_    128
#define W_    128
#define HW    16384
#define HEADS 8
#define HD    24
#define C3    576
#define HID   510
#define HID2  1020
#define KPAD  512

// ---------------- scratch (device globals; no allocs) ----------------
__device__ __nv_bfloat16 gb_big[(size_t)B_ * HID2 * HW];
__device__ __nv_bfloat16 gb_qkv[(size_t)B_ * C3 * HW];
__device__ __nv_bfloat16 gb_y  [(size_t)B_ * C_ * HW];
__device__ float g_sumsq[B_ * 2 * C_];
__device__ float g_attn [B_ * HEADS * HD * HD];
__device__ __nv_bfloat16 gw_qkv[640 * 192];
__device__ __nv_bfloat16 gw_proj[256 * 192];
__device__ __nv_bfloat16 gw_in [1024 * 192];
__device__ __nv_bfloat16 gw_out[256 * KPAD];

__device__ __forceinline__ unsigned bf2u(__nv_bfloat162 h) { return *(unsigned*)&h; }

// ---------------- prep ----------------
__global__ void prep_kernel(const float* __restrict__ wqkv, const float* __restrict__ wproj,
                            const float* __restrict__ win,  const float* __restrict__ wout) {
    const int N1 = 640 * 192, N2 = 256 * 192, N3 = 1024 * 192, N4 = 256 * KPAD;
    const int N5 = B_ * 2 * C_, N6 = B_ * HEADS * HD * HD;
    const int TOT = N1 + N2 + N3 + N4 + N5 + N6;
    for (int i = blockIdx.x * blockDim.x + threadIdx.x; i < TOT; i += gridDim.x * blockDim.x) {
        int j = i;
        if (j < N1) { int m = j / 192, k = j - m * 192;
            gw_qkv[j] = __float2bfloat16(m < C3 ? wqkv[m * 192 + k] : 0.f); continue; }
        j -= N1;
        if (j < N2) { int m = j / 192, k = j - m * 192;
            gw_proj[j] = __float2bfloat16(m < C_ ? wproj[m * 192 + k] : 0.f); continue; }
        j -= N2;
        if (j < N3) { int m = j / 192, k = j - m * 192;
            gw_in[j] = __float2bfloat16(m < HID2 ? win[m * 192 + k] : 0.f); continue; }
        j -= N3;
        if (j < N4) { int m = j / KPAD, k = j - m * KPAD;
            gw_out[j] = __float2bfloat16((m < C_ && k < HID) ? wout[m * HID + k] : 0.f); continue; }
        j -= N4;
        if (j < N5) { g_sumsq[j] = 0.f; continue; }
        j -= N5;
        g_attn[j] = 0.f;
    }
}

// ---------------- channel LayerNorm: fp32 in -> bf16 out (4 pixels/thread) ----------------
__global__ __launch_bounds__(256) void ln_bf_kernel(const float* __restrict__ in,
                                                    const float* __restrict__ w,
                                                    const float* __restrict__ bias,
                                                    __nv_bfloat16* __restrict__ outp) {
    int idx = blockIdx.x * blockDim.x + threadIdx.x;
    int b = idx >> 12;
    int p = (idx & 4095) << 2;
    const float* src = in + (size_t)b * C_ * HW + p;
    float4 s = make_float4(0.f, 0.f, 0.f, 0.f);
    float4 q = make_float4(0.f, 0.f, 0.f, 0.f);
#pragma unroll 8
    for (int c = 0; c < C_; c++) {
        float4 v = *(const float4*)(src + (size_t)c * HW);
        s.x += v.x; s.y += v.y; s.z += v.z; s.w += v.w;
        q.x += v.x * v.x; q.y += v.y * v.y; q.z += v.z * v.z; q.w += v.w * v.w;
    }
    const float ic = 1.0f / C_;
    float4 mu = make_float4(s.x * ic, s.y * ic, s.z * ic, s.w * ic);
    float4 rs;
    rs.x = rsqrtf(q.x * ic - mu.x * mu.x + 1e-5f);
    rs.y = rsqrtf(q.y * ic - mu.y * mu.y + 1e-5f);
    rs.z = rsqrtf(q.z * ic - mu.z * mu.z + 1e-5f);
    rs.w = rsqrtf(q.w * ic - mu.w * mu.w + 1e-5f);
    __nv_bfloat16* dst = outp + (size_t)b * C_ * HW + p;
#pragma unroll 8
    for (int c = 0; c < C_; c++) {
        float4 v = *(const float4*)(src + (size_t)c * HW);
        float wc = w[c], bc = bias[c];
        __nv_bfloat162 h0, h1;
        h0.x = __float2bfloat16((v.x - mu.x) * rs.x * wc + bc);
        h0.y = __float2bfloat16((v.y - mu.y) * rs.y * wc + bc);
        h1.x = __float2bfloat16((v.z - mu.z) * rs.z * wc + bc);
        h1.y = __float2bfloat16((v.w - mu.w) * rs.w * wc + bc);
        uint2 u; u.x = bf2u(h0); u.y = bf2u(h1);
        *(uint2*)(dst + (size_t)c * HW) = u;
    }
}

// ---------------- bf16 tensor-core GEMM (templated K/mode) ----------------
#define BM 128
#define BN 128
#define BK 32
#define ASTR 40
#define BSTR 136

__device__ __forceinline__ void cpa16(unsigned dst, const void* src) {
    asm volatile("cp.async.cg.shared.global [%0], [%1], 16;\n" :: "r"(dst), "l"(src));
}

template<int K, int MODE>
__global__ __launch_bounds__(256) void gemm_bf(
    const __nv_bfloat16* __restrict__ A,
    const __nv_bfloat16* __restrict__ Bact, int bStrideCh,
    __nv_bfloat16* __restrict__ OutBf, int outStrideCh,
    float* __restrict__ OutF, const float* __restrict__ Res, int M)
{
    __shared__ __align__(16) __nv_bfloat16 As[2][BM * ASTR];
    __shared__ __align__(16) __nv_bfloat16 Bs[2][BK * BSTR];

    const int b     = blockIdx.z;
    const int nBase = blockIdx.x * BN;
    const int mBase = blockIdx.y * BM;
    const int tid   = threadIdx.x;
    const int lane  = tid & 31, wid = tid >> 5;
    const int warpM = wid >> 2, warpN = wid & 3;
    const int g = lane >> 2, tig = lane & 3;

    const __nv_bfloat16* bsrc = Bact + (size_t)b * bStrideCh * HW;

    float acc[4][4][4];
#pragma unroll
    for (int i = 0; i < 4; i++)
#pragma unroll
        for (int j = 0; j < 4; j++)
#pragma unroll
            for (int r = 0; r < 4; r++) acc[i][j][r] = 0.f;

    constexpr int nIter = K / BK;

    auto load_stage = [&](int s, int k0) {
        unsigned aBase = (unsigned)__cvta_generic_to_shared(&As[s][0]);
        unsigned bBase = (unsigned)__cvta_generic_to_shared(&Bs[s][0]);
#pragma unroll
        for (int u = 0; u < 2; u++) {
            int t  = tid * 2 + u;
            int ar = t >> 2, ac = (t & 3) * 8;
            cpa16(aBase + (unsigned)(ar * ASTR + ac) * 2u,
                  A + (size_t)(mBase + ar) * K + k0 + ac);
            int br = t >> 4, bc = (t & 15) * 8;
            cpa16(bBase + (unsigned)(br * BSTR + bc) * 2u,
                  bsrc + (size_t)(k0 + br) * HW + nBase + bc);
        }
    };

    load_stage(0, 0);
    asm volatile("cp.async.commit_group;\n");
    load_stage(1, BK);
    asm volatile("cp.async.commit_group;\n");

    const int aRowSel = ((lane >> 3) & 1) * 8 + (lane & 7);
    const int aKSel   = (lane >> 4) * 8;
    const int bKSel   = ((lane >> 3) & 1) * 8 + (lane & 7);
    const int bNSel   = (lane >> 4) * 8;

#pragma unroll 2
    for (int it = 0; it < nIter; it++) {
        asm volatile("cp.async.wait_group 1;\n");
        __syncthreads();
        const int s = it & 1;
        unsigned aB = (unsigned)__cvta_generic_to_shared(&As[s][0]);
        unsigned bB = (unsigned)__cvta_generic_to_shared(&Bs[s][0]);

#pragma unroll
        for (int ks = 0; ks < 2; ks++) {
            const int kb = ks * 16;
            unsigned af[4][4];
#pragma unroll
            for (int mt = 0; mt < 4; mt++) {
                int mloc = warpM * 64 + mt * 16 + aRowSel;
                unsigned addr = aB + (unsigned)(mloc * ASTR + kb + aKSel) * 2u;
                asm volatile("ldmatrix.sync.aligned.m8n8.x4.shared.b16 {%0,%1,%2,%3}, [%4];"
                             : "=r"(af[mt][0]), "=r"(af[mt][1]), "=r"(af[mt][2]), "=r"(af[mt][3])
                             : "r"(addr));
            }
            unsigned bfr[4][2];
#pragma unroll
            for (int half = 0; half < 2; half++) {
                int kloc = kb + bKSel;
                int nloc = warpN * 32 + half * 16 + bNSel;
                unsigned addr = bB + (unsigned)(kloc * BSTR + nloc) * 2u;
                unsigned r0, r1, r2, r3;
                asm volatile("ldmatrix.sync.aligned.m8n8.x4.trans.shared.b16 {%0,%1,%2,%3}, [%4];"
                             : "=r"(r0), "=r"(r1), "=r"(r2), "=r"(r3) : "r"(addr));
                bfr[half * 2 + 0][0] = r0; bfr[half * 2 + 0][1] = r1;
                bfr[half * 2 + 1][0] = r2; bfr[half * 2 + 1][1] = r3;
            }
#pragma unroll
            for (int mt = 0; mt < 4; mt++)
#pragma unroll
                for (int j = 0; j < 4; j++) {
                    asm volatile(
                        "mma.sync.aligned.m16n8k16.row.col.f32.bf16.bf16.f32 "
                        "{%0,%1,%2,%3}, {%4,%5,%6,%7}, {%8,%9}, {%0,%1,%2,%3};"
                        : "+f"(acc[mt][j][0]), "+f"(acc[mt][j][1]),
                          "+f"(acc[mt][j][2]), "+f"(acc[mt][j][3])
                        : "r"(af[mt][0]), "r"(af[mt][1]), "r"(af[mt][2]), "r"(af[mt][3]),
                          "r"(bfr[j][0]), "r"(bfr[j][1]));
                }
        }
        __syncthreads();
        int knext = (it + 2) * BK;
        if (knext < K) load_stage(s, knext);
        asm volatile("cp.async.commit_group;\n");
    }

#pragma unroll
    for (int mt = 0; mt < 4; mt++) {
        int mLo = mBase + warpM * 64 + mt * 16 + g;
        int mHi = mLo + 8;
#pragma unroll
        for (int j = 0; j < 4; j++) {
            int n = nBase + warpN * 32 + j * 8 + 2 * tig;
            if (MODE == 0) {
                if (mLo < M) {
                    __nv_bfloat162 h;
                    h.x = __float2bfloat16(acc[mt][j][0]);
                    h.y = __float2bfloat16(acc[mt][j][1]);
                    *(__nv_bfloat162*)(OutBf + ((size_t)b * outStrideCh + mLo) * HW + n) = h;
                }
                if (mHi < M) {
                    __nv_bfloat162 h;
                    h.x = __float2bfloat16(acc[mt][j][2]);
                    h.y = __float2bfloat16(acc[mt][j][3]);
                    *(__nv_bfloat162*)(OutBf + ((size_t)b * outStrideCh + mHi) * HW + n) = h;
                }
            } else {
                if (mLo < M) {
                    size_t off = ((size_t)b * M + mLo) * HW + n;
                    float2 v = make_float2(acc[mt][j][0], acc[mt][j][1]);
                    if (MODE == 1) { float2 r = *(const float2*)(Res + off); v.x += r.x; v.y += r.y; }
                    else           { float2 r = *(const float2*)(OutF + off); v.x += r.x; v.y += r.y; }
                    *(float2*)(OutF + off) = v;
                }
                if (mHi < M) {
                    size_t off = ((size_t)b * M + mHi) * HW + n;
                    float2 v = make_float2(acc[mt][j][2], acc[mt][j][3]);
                    if (MODE == 1) { float2 r = *(const float2*)(Res + off); v.x += r.x; v.y += r.y; }
                    else           { float2 r = *(const float2*)(OutF + off); v.x += r.x; v.y += r.y; }
                    *(float2*)(OutF + off) = v;
                }
            }
        }
    }
}

// ---------------- register-direct 3x3 row loader: 10 floats for 8 outputs ----------------
__device__ __forceinline__ void load_row10(float* row, const __nv_bfloat16* base,
                                           int y, int c0) {
    if (y >= 0 && y < H_) {
        const __nv_bfloat16* rp = base + y * W_;
        uint4 u = *(const uint4*)(rp + c0);
        __nv_bfloat162* hp = (__nv_bfloat162*)&u;
        float2 f0 = __bfloat1622float2(hp[0]);
        float2 f1 = __bfloat1622float2(hp[1]);
        float2 f2 = __bfloat1622float2(hp[2]);
        float2 f3 = __bfloat1622float2(hp[3]);
        row[1] = f0.x; row[2] = f0.y; row[3] = f1.x; row[4] = f1.y;
        row[5] = f2.x; row[6] = f2.y; row[7] = f3.x; row[8] = f3.y;
        row[0] = (c0 > 0)       ? __bfloat162float(rp[c0 - 1]) : 0.f;
        row[9] = (c0 + 8 < W_)  ? __bfloat162float(rp[c0 + 8]) : 0.f;
    } else {
#pragma unroll
        for (int t = 0; t < 10; t++) row[t] = 0.f;
    }
}

// ---------------- depthwise 3x3 qkv (register-direct) + q/k sumsq ----------------
__global__ __launch_bounds__(256) void dwqkv_kernel(const float* __restrict__ wdw) {
    const int y0 = blockIdx.x * 16, c = blockIdx.y, b = blockIdx.z, tid = threadIdx.x;
    const int r = tid >> 4, c0 = (tid & 15) * 8;
    const int y = y0 + r;
    const __nv_bfloat16* src = gb_big + ((size_t)b * HID2 + c) * HW;
    float row[3][10];
#pragma unroll
    for (int rr = 0; rr < 3; rr++) load_row10(row[rr], src, y + rr - 1, c0);

    const float* wp = wdw + c * 9;
    const float w0 = wp[0], w1 = wp[1], w2 = wp[2], w3 = wp[3], w4 = wp[4],
                w5 = wp[5], w6 = wp[6], w7 = wp[7], w8 = wp[8];
    float sq = 0.f;
    __nv_bfloat162 o[4];
#pragma unroll
    for (int x = 0; x < 8; x++) {
        float v = w0 * row[0][x] + w1 * row[0][x + 1] + w2 * row[0][x + 2]
                + w3 * row[1][x] + w4 * row[1][x + 1] + w5 * row[1][x + 2]
                + w6 * row[2][x] + w7 * row[2][x + 1] + w8 * row[2][x + 2];
        __nv_bfloat16 hb = __float2bfloat16(v);
        float vb = __bfloat162float(hb);
        sq += vb * vb;
        if (x & 1) o[x >> 1].y = hb; else o[x >> 1].x = hb;
    }
    __nv_bfloat16* dst = gb_qkv + ((size_t)b * C3 + c) * HW;
    uint4 pack;
    pack.x = bf2u(o[0]); pack.y = bf2u(o[1]); pack.z = bf2u(o[2]); pack.w = bf2u(o[3]);
    *(uint4*)(dst + y * W_ + c0) = pack;

    if (c < 2 * C_) {
#pragma unroll
        for (int off = 16; off; off >>= 1) sq += __shfl_xor_sync(0xffffffffu, sq, off);
        __shared__ float ws[8];
        if ((tid & 31) == 0) ws[tid >> 5] = sq;
        __syncthreads();
        if (tid == 0) {
            float t = 0.f;
#pragma unroll
            for (int i = 0; i < 8; i++) t += ws[i];
            atomicAdd(&g_sumsq[b * 2 * C_ + c], t);
        }
    }
}

// ---------------- attention partial scores: smem-staged, p-split, atomics ----------------
#define PSPLIT 8
__global__ __launch_bounds__(256) void attn_part_kernel() {
    const int ps = blockIdx.x, h = blockIdx.y, b = blockIdx.z;
    const int tid = threadIdx.x, warp = tid >> 5, lane = tid & 31;
    const __nv_bfloat16* base = gb_qkv + (size_t)b * C3 * HW;
    const __nv_bfloat16* qb = base + (size_t)(h * HD) * HW;
    const __nv_bfloat16* kb = base + (size_t)(C_ + h * HD) * HW;
    __shared__ float qs[24][132];
    __shared__ float ks[24][132];

    float acc[3][24];
#pragma unroll
    for (int r = 0; r < 3; r++)
#pragma unroll
        for (int c = 0; c < 24; c++) acc[r][c] = 0.f;

    const int p0 = ps * (HW / PSPLIT);
    for (int t = 0; t < (HW / PSPLIT) / 128; t++) {
        int pt = p0 + t * 128;
        __syncthreads();
        for (int i = tid; i < 768; i += 256) {
            int ch = i >> 5, seg = (i & 31) * 4;
            uint2 u = *(const uint2*)(kb + (size_t)ch * HW + pt + seg);
            float2 f0 = __bfloat1622float2(*(__nv_bfloat162*)&u.x);
            float2 f1 = __bfloat1622float2(*(__nv_bfloat162*)&u.y);
            *(float4*)&ks[ch][seg] = make_float4(f0.x, f0.y, f1.x, f1.y);
            uint2 v = *(const uint2*)(qb + (size_t)ch * HW + pt + seg);
            float2 g0 = __bfloat1622float2(*(__nv_bfloat162*)&v.x);
            float2 g1 = __bfloat1622float2(*(__nv_bfloat162*)&v.y);
            *(float4*)&qs[ch][seg] = make_float4(g0.x, g0.y, g1.x, g1.y);
        }
        __syncthreads();
        float4 qv[3];
#pragma unroll
        for (int r = 0; r < 3; r++)
            qv[r] = *(const float4*)&qs[warp * 3 + r][lane * 4];
#pragma unroll
        for (int ch = 0; ch < 24; ch++) {
            float4 kv = *(const float4*)&ks[ch][lane * 4];
#pragma unroll
            for (int r = 0; r < 3; r++)
                acc[r][ch] += qv[r].x * kv.x + qv[r].y * kv.y + qv[r].z * kv.z + qv[r].w * kv.w;
        }
    }
#pragma unroll
    for (int r = 0; r < 3; r++)
#pragma unroll
        for (int c = 0; c < 24; c++)
#pragma unroll
            for (int off = 16; off; off >>= 1)
                acc[r][c] += __shfl_xor_sync(0xffffffffu, acc[r][c], off);
    if (lane == 0) {
        float* ap = g_attn + (((size_t)(b * HEADS + h)) * HD + warp * 3) * HD;
#pragma unroll
        for (int r = 0; r < 3; r++)
#pragma unroll
            for (int c = 0; c < 24; c++)
                atomicAdd(&ap[r * HD + c], acc[r][c]);
    }
}

// ---------------- softmax finalize ----------------
__global__ void softmax_kernel(const float* __restrict__ temp) {
    int i = blockIdx.x * blockDim.x + threadIdx.x;
    if (i >= B_ * HEADS * HD) return;
    int d = i % HD;
    int bh = i / HD;
    int h = bh % HEADS, b = bh / HEADS;
    float* rowp = g_attn + (size_t)i * HD;
    float sq = g_sumsq[b * 2 * C_ + h * HD + d];
    float rq = 1.0f / fmaxf(sqrtf(sq), 1e-12f);
    float t = temp[h];
    float row[24];
    float mx = -3.4e38f;
#pragma unroll
    for (int c = 0; c < 24; c++) {
        float sk = g_sumsq[b * 2 * C_ + C_ + h * HD + c];
        float rk = 1.0f / fmaxf(sqrtf(sk), 1e-12f);
        row[c] = rowp[c] * rq * rk * t;
        mx = fmaxf(mx, row[c]);
    }
    float sum = 0.f;
#pragma unroll
    for (int c = 0; c < 24; c++) { row[c] = expf(row[c] - mx); sum += row[c]; }
    float inv = 1.0f / sum;
#pragma unroll
    for (int c = 0; c < 24; c++) rowp[c] = row[c] * inv;
}

// ---------------- out = attn @ v -> gb_y (bf16), 4 pixels/thread ----------------
__global__ __launch_bounds__(256) void av_kernel() {
    int tid = threadIdx.x;
    int p = blockIdx.x * 1024 + tid * 4;
    int h = blockIdx.y, b = blockIdx.z;
    __shared__ float A[HD * HD];
    const float* ap = g_attn + ((size_t)(b * HEADS + h)) * HD * HD;
    for (int i = tid; i < HD * HD; i += 256) A[i] = ap[i];
    __syncthreads();
    const __nv_bfloat16* vb = gb_qkv + (size_t)b * C3 * HW + (size_t)(2 * C_ + h * HD) * HW;
    float4 v[24];
#pragma unroll
    for (int c = 0; c < 24; c++) {
        uint2 u = *(const uint2*)(vb + (size_t)c * HW + p);
        float2 f0 = __bfloat1622float2(*(__nv_bfloat162*)&u.x);
        float2 f1 = __bfloat1622float2(*(__nv_bfloat162*)&u.y);
        v[c] = make_float4(f0.x, f0.y, f1.x, f1.y);
    }
    __nv_bfloat16* ob = gb_y + (size_t)b * C_ * HW + (size_t)(h * HD) * HW;
#pragma unroll
    for (int d = 0; d < 24; d++) {
        float s0 = 0.f, s1 = 0.f, s2 = 0.f, s3 = 0.f;
#pragma unroll
        for (int c = 0; c < 24; c++) {
            float a = A[d * 24 + c];
            s0 += a * v[c].x; s1 += a * v[c].y; s2 += a * v[c].z; s3 += a * v[c].w;
        }
        __nv_bfloat162 h0, h1;
        h0.x = __float2bfloat16(s0); h0.y = __float2bfloat16(s1);
        h1.x = __float2bfloat16(s2); h1.y = __float2bfloat16(s3);
        uint2 u; u.x = bf2u(h0); u.y = bf2u(h1);
        *(uint2*)(ob + (size_t)d * HW + p) = u;
    }
}

// ---------------- FFN depthwise 3x3 + GELU gate (register-direct) ----------------
__global__ __launch_bounds__(256) void dwgate_kernel(const float* __restrict__ wdw) {
    const int y0 = blockIdx.x * 16, j = blockIdx.y, b = blockIdx.z, tid = threadIdx.x;
    const int r = tid >> 4, c0 = (tid & 15) * 8;
    const int y = y0 + r;
    __nv_bfloat16* dst = gb_qkv + ((size_t)b * C3 + j) * HW;
    if (j >= HID) {
        uint4 z = make_uint4(0u, 0u, 0u, 0u);
        *(uint4*)(dst + y * W_ + c0) = z;
        return;
    }
    const __nv_bfloat16* src1 = gb_big + ((size_t)b * HID2 + j) * HW;
    const __nv_bfloat16* src2 = gb_big + ((size_t)b * HID2 + j + HID) * HW;
    float r1[3][10], r2[3][10];
#pragma unroll
    for (int rr = 0; rr < 3; rr++) {
        load_row10(r1[rr], src1, y + rr - 1, c0);
        load_row10(r2[rr], src2, y + rr - 1, c0);
    }
    const float* wa = wdw + j * 9;
    const float* wb = wdw + (j + HID) * 9;
    const float a0 = wa[0], a1 = wa[1], a2 = wa[2], a3 = wa[3], a4 = wa[4],
                a5 = wa[5], a6 = wa[6], a7 = wa[7], a8 = wa[8];
    const float b0 = wb[0], b1 = wb[1], b2 = wb[2], b3 = wb[3], b4 = wb[4],
                b5 = wb[5], b6 = wb[6], b7 = wb[7], b8 = wb[8];
    __nv_bfloat162 o[4];
#pragma unroll
    for (int x = 0; x < 8; x++) {
        float v1 = a0 * r1[0][x] + a1 * r1[0][x + 1] + a2 * r1[0][x + 2]
                 + a3 * r1[1][x] + a4 * r1[1][x + 1] + a5 * r1[1][x + 2]
                 + a6 * r1[2][x] + a7 * r1[2][x + 1] + a8 * r1[2][x + 2];
        float v2 = b0 * r2[0][x] + b1 * r2[0][x + 1] + b2 * r2[0][x + 2]
                 + b3 * r2[1][x] + b4 * r2[1][x + 1] + b5 * r2[1][x + 2]
                 + b6 * r2[2][x] + b7 * r2[2][x + 1] + b8 * r2[2][x + 2];
        float gl = 0.5f * v1 * (1.0f + erff(v1 * 0.70710678118654752440f));
        __nv_bfloat16 hb = __float2bfloat16(gl * v2);
        if (x & 1) o[x >> 1].y = hb; else o[x >> 1].x = hb;
    }
    uint4 pack;
    pack.x = bf2u(o[0]); pack.y = bf2u(o[1]); pack.z = bf2u(o[2]); pack.w = bf2u(o[3]);
    *(uint4*)(dst + y * W_ + c0) = pack;
}

// ---------------- launch ----------------
extern "C" void kernel_launch(void* const* d_in, const int* in_sizes, int n_in,
                              void* d_out, int out_size) {
    const float* x      = (const float*)d_in[0];
    const float* temp   = (const float*)d_in[1];
    const float* ln1w   = (const float*)d_in[2];
    const float* ln1b   = (const float*)d_in[3];
    const float* ln2w   = (const float*)d_in[4];
    const float* ln2b   = (const float*)d_in[5];
    const float* wqkv   = (const float*)d_in[6];
    const float* wqkvdw = (const float*)d_in[7];
    const float* wproj  = (const float*)d_in[8];
    const float* win    = (const float*)d_in[9];
    const float* wdw    = (const float*)d_in[10];
    const float* wout   = (const float*)d_in[11];
    float* out = (float*)d_out;

    __nv_bfloat16 *pBig, *pQkv, *pY, *pWqkv, *pWproj, *pWin, *pWout;
    cudaGetSymbolAddress((void**)&pBig,  gb_big);
    cudaGetSymbolAddress((void**)&pQkv,  gb_qkv);
    cudaGetSymbolAddress((void**)&pY,    gb_y);
    cudaGetSymbolAddress((void**)&pWqkv, gw_qkv);
    cudaGetSymbolAddress((void**)&pWproj,gw_proj);
    cudaGetSymbolAddress((void**)&pWin,  gw_in);
    cudaGetSymbolAddress((void**)&pWout, gw_out);

    prep_kernel<<<512, 256>>>(wqkv, wproj, win, wout);

    // --- attention branch ---
    ln_bf_kernel<<<(B_ * HW / 4) / 256, 256>>>(x, ln1w, ln1b, pY);
    gemm_bf<192, 0><<<dim3(128, 5, B_), 256>>>(pWqkv, pY, C_, pBig, HID2, nullptr, nullptr, C3);
    dwqkv_kernel<<<dim3(8, C3, B_), 256>>>(wqkvdw);
    attn_part_kernel<<<dim3(PSPLIT, HEADS, B_), 256>>>();
    softmax_kernel<<<3, 256>>>(temp);
    av_kernel<<<dim3(HW / 1024, HEADS, B_), 256>>>();
    gemm_bf<192, 1><<<dim3(128, 2, B_), 256>>>(pWproj, pY, C_, nullptr, 0, out, x, C_);

    // --- FFN branch ---
    ln_bf_kernel<<<(B_ * HW / 4) / 256, 256>>>(out, ln2w, ln2b, pY);
    gemm_bf<192, 0><<<dim3(128, 8, B_), 256>>>(pWin, pY, C_, pBig, HID2, nullptr, nullptr, HID2);
    dwgate_kernel<<<dim3(8, KPAD, B_), 256>>>(wdw);
    gemm_bf<512, 2><<<dim3(128, 2, B_), 256>>>(pWout, pQkv, C3, nullptr, 0, out, nullptr, C_);
}